// round 11
// baseline (speedup 1.0000x reference)
#include <cuda_runtime.h>
#include <cuda_bf16.h>
#include <math.h>

#define GN 16384
#define ECH 256
#define NB 8
#define HB 4
#define NSPLIT 16
static const size_t BSTR = (size_t)ECH * GN;
static const size_t TOT4 = (size_t)HB * BSTR;
typedef __nv_bfloat16 bf16;
typedef __nv_bfloat162 bf162;

__device__ float g_emb[33554432];
__device__ float g_pre[33554432];
__device__ float g_pu[HB * NSPLIT * 256 * 256];
__device__ float g_plw[HB * NSPLIT * 256 * 512];
__device__ bf16 g_fh[33554432], g_fl[33554432];
__device__ bf16 g_nh[33554432], g_nl[33554432];
__device__ bf16 g_qkvh[50331648], g_qkvl[50331648];
__device__ bf16 g_th[33554432], g_tl[33554432];   // 8 batches: [0..3]=lower ca, [4..7]=upper t
__device__ bf16 g_kvh[8388608], g_kvl[8388608];
__device__ bf16 g_suh[1048576], g_sul[1048576];
__device__ bf16 g_slh[1048576], g_sll[1048576];
__device__ bf16 g_wh[524288], g_wl[524288];

__device__ __forceinline__ unsigned s2u(const void* p) {
    return (unsigned)__cvta_generic_to_shared(p);
}
__device__ __forceinline__ void cpa16(unsigned dst, const void* src) {
    asm volatile("cp.async.cg.shared.global [%0], [%1], 16;" :: "r"(dst), "l"(src));
}
__device__ __forceinline__ void cp_commit() { asm volatile("cp.async.commit_group;"); }
__device__ __forceinline__ void cp_wait0() { asm volatile("cp.async.wait_group 0;" ::: "memory"); }
__device__ __forceinline__ void cp_wait1() { asm volatile("cp.async.wait_group 1;" ::: "memory"); }

__device__ __forceinline__ void ldm4(unsigned* r, unsigned a) {
    asm volatile("ldmatrix.sync.aligned.m8n8.x4.shared.b16 {%0,%1,%2,%3}, [%4];"
                 : "=r"(r[0]), "=r"(r[1]), "=r"(r[2]), "=r"(r[3]) : "r"(a));
}
__device__ __forceinline__ void ldm4t(unsigned* r, unsigned a) {
    asm volatile("ldmatrix.sync.aligned.m8n8.x4.trans.shared.b16 {%0,%1,%2,%3}, [%4];"
                 : "=r"(r[0]), "=r"(r[1]), "=r"(r[2]), "=r"(r[3]) : "r"(a));
}
__device__ __forceinline__ void mma_bf16(float* c, const unsigned* a, unsigned b0, unsigned b1) {
    asm volatile(
        "mma.sync.aligned.m16n8k16.row.col.f32.bf16.bf16.f32 "
        "{%0,%1,%2,%3},{%4,%5,%6,%7},{%8,%9},{%0,%1,%2,%3};"
        : "+f"(c[0]), "+f"(c[1]), "+f"(c[2]), "+f"(c[3])
        : "r"(a[0]), "r"(a[1]), "r"(a[2]), "r"(a[3]), "r"(b0), "r"(b1));
}
__device__ __forceinline__ void split2(float a, float b, bf162& h, bf162& l) {
    h = __floats2bfloat162_rn(a, b);
    float2 hf = __bfloat1622float2(h);
    l = __floats2bfloat162_rn(a - hf.x, b - hf.y);
}
__device__ __forceinline__ float gelu_exact(float x) {
    return 0.5f * x * (1.0f + erff(x * 0.70710678118654752f));
}
__device__ __forceinline__ float brsum(float v, float* sb) {
    int t = threadIdx.x;
    sb[t] = v; __syncthreads();
    for (int s = 128; s > 0; s >>= 1) { if (t < s) sb[t] += sb[t + s]; __syncthreads(); }
    float r = sb[0]; __syncthreads(); return r;
}
__device__ __forceinline__ float brmax(float v, float* sb) {
    int t = threadIdx.x;
    sb[t] = v; __syncthreads();
    for (int s = 128; s > 0; s >>= 1) { if (t < s) sb[t] = fmaxf(sb[t], sb[t + s]); __syncthreads(); }
    float r = sb[0]; __syncthreads(); return r;
}

#define CBUF 37888
#define CSMEM3 113664          // 3 buffers, single-sync pipeline
#define NBUF 40960
#define NSMEM 81920

// conv1x1 GEMM: C[b](M x GN) = A[b](M x K) @ B[b](K x GN); M = 128*gridDim.y
// epi bits: 1 gelu, 2 +R, 4 split-out, 8 fp32-out, 16 dual-weight (b<4 -> slot7, else slot5)
__global__ __launch_bounds__(256, 2)
void gemm_cp(const bf16* __restrict__ Ah, const bf16* __restrict__ Al, size_t aBs,
             const bf16* __restrict__ Bh, const bf16* __restrict__ Bl, size_t bBs,
             float* __restrict__ C, bf16* __restrict__ Ch, bf16* __restrict__ Cl,
             size_t cBs, size_t oGrp, const float* __restrict__ R,
             int K, int epi) {
    extern __shared__ char smem[];
    int tid = threadIdx.x, wid = tid >> 5, lane = tid & 31;
    int wm = wid & 1, wn = wid >> 1;
    int oBase = blockIdx.y * 128, nBase = blockIdx.x * 128;
    int b = blockIdx.z;
    Ah += (size_t)b * aBs; Al += (size_t)b * aBs;
    if (epi & 16) {
        size_t sel = (size_t)((b < 4) ? 7 : 5) * 65536;
        Ah += sel; Al += sel;
    }
    Bh += (size_t)b * bBs; Bl += (size_t)b * bBs;

    unsigned sb0 = s2u(smem);
    auto stage = [&](int kk, int buf) {
        unsigned base = sb0 + buf * CBUF;
#pragma unroll
        for (int i = 0; i < 8; i++) {
            int c = tid + 256 * i;
            if (i < 4) {
                int p = c >> 9, r = (c >> 2) & 127, s = c & 3;
                const bf16* src = (p ? Al : Ah) + (size_t)(oBase + r) * K + kk + s * 8;
                cpa16(base + p * 10240 + r * 80 + s * 16, src);
            } else {
                int c2 = c - 1024;
                int p = c2 >> 9, r = (c2 >> 4) & 31, s = c2 & 15;
                const bf16* src = (p ? Bl : Bh) + (size_t)(kk + r) * GN + nBase + s * 8;
                cpa16(base + 20480 + p * 8704 + r * 272 + s * 16, src);
            }
        }
        cp_commit();
    };

    float acc[4][4][4];
#pragma unroll
    for (int i = 0; i < 4; i++)
#pragma unroll
        for (int j = 0; j < 4; j++)
#pragma unroll
            for (int q = 0; q < 4; q++) acc[i][j][q] = 0.0f;

    unsigned aRow = (unsigned)(wm * 64 + (lane & 15));
    unsigned aKof = (unsigned)((lane >> 4) * 8);
    unsigned bKrow = (unsigned)((lane & 7) + ((lane >> 3) & 1) * 8);
    unsigned bNcol = (unsigned)(wn * 32 + ((lane >> 4) & 1) * 8);

    int KT = K >> 5;
    stage(0, 0);
    if (KT > 1) stage(32, 1);
    int buf = 0;
    for (int t = 0; t < KT; t++) {
        if (t + 2 < KT) cp_wait1(); else cp_wait0();
        __syncthreads();
        if (t + 2 < KT) {
            int nb = buf + 2; if (nb >= 3) nb -= 3;
            stage((t + 2) * 32, nb);
        }

        const bf16* sA0 = (const bf16*)(smem + buf * CBUF);
        const bf16* sA1 = (const bf16*)(smem + buf * CBUF + 10240);
        const bf16* sB0 = (const bf16*)(smem + buf * CBUF + 20480);
        const bf16* sB1 = (const bf16*)(smem + buf * CBUF + 29184);
#pragma unroll
        for (int ks = 0; ks < 32; ks += 16) {
            unsigned ah[4][4], bh[2][4];
#pragma unroll
            for (int mt = 0; mt < 4; mt++)
                ldm4(ah[mt], s2u(&sA0[(aRow + mt * 16) * 40 + ks + aKof]));
#pragma unroll
            for (int n2 = 0; n2 < 2; n2++)
                ldm4t(bh[n2], s2u(&sB0[(bKrow + ks) * 136 + bNcol + n2 * 16]));
#pragma unroll
            for (int mt = 0; mt < 4; mt++)
#pragma unroll
                for (int nt = 0; nt < 4; nt++)
                    mma_bf16(acc[mt][nt], ah[mt], bh[nt >> 1][(nt & 1) * 2],
                             bh[nt >> 1][(nt & 1) * 2 + 1]);
            unsigned bl[2][4];
#pragma unroll
            for (int n2 = 0; n2 < 2; n2++)
                ldm4t(bl[n2], s2u(&sB1[(bKrow + ks) * 136 + bNcol + n2 * 16]));
#pragma unroll
            for (int mt = 0; mt < 4; mt++)
#pragma unroll
                for (int nt = 0; nt < 4; nt++)
                    mma_bf16(acc[mt][nt], ah[mt], bl[nt >> 1][(nt & 1) * 2],
                             bl[nt >> 1][(nt & 1) * 2 + 1]);
            unsigned al[4][4];
#pragma unroll
            for (int mt = 0; mt < 4; mt++)
                ldm4(al[mt], s2u(&sA1[(aRow + mt * 16) * 40 + ks + aKof]));
#pragma unroll
            for (int mt = 0; mt < 4; mt++)
#pragma unroll
                for (int nt = 0; nt < 4; nt++)
                    mma_bf16(acc[mt][nt], al[mt], bh[nt >> 1][(nt & 1) * 2],
                             bh[nt >> 1][(nt & 1) * 2 + 1]);
        }
        buf++; if (buf >= 3) buf -= 3;
    }

    int g = lane >> 2, tg = lane & 3;
#pragma unroll
    for (int mt = 0; mt < 4; mt++) {
#pragma unroll
        for (int nt = 0; nt < 4; nt++) {
            int r0 = oBase + wm * 64 + mt * 16 + g;
            int col = nBase + wn * 32 + nt * 8 + tg * 2;
            float* c = acc[mt][nt];
#pragma unroll
            for (int h2 = 0; h2 < 2; h2++) {
                int rr = r0 + h2 * 8;
                size_t base = (size_t)(rr >> 8) * oGrp + (size_t)b * cBs
                            + (size_t)(rr & 255) * GN + col;
                float o0 = c[2 * h2], o1 = c[2 * h2 + 1];
                if (epi & 2) {
                    float2 rv = *(const float2*)&R[base];
                    o0 += rv.x; o1 += rv.y;
                }
                if (epi & 1) { o0 = gelu_exact(o0); o1 = gelu_exact(o1); }
                if (epi & 8) *(float2*)&C[base] = make_float2(o0, o1);
                if (epi & 4) {
                    bf162 h, l;
                    split2(o0, o1, h, l);
                    *(bf162*)&Ch[base] = h;
                    *(bf162*)&Cl[base] = l;
                }
            }
        }
    }
}

__global__ __launch_bounds__(256, 2)
void gemmnt_cp(const bf16* __restrict__ Qh, const bf16* __restrict__ Ql, size_t qBs,
               const bf16* __restrict__ Kh, const bf16* __restrict__ Kl, size_t kBs,
               float* __restrict__ P, int J) {
    extern __shared__ char smem[];
    int tid = threadIdx.x, wid = tid >> 5, lane = tid & 31;
    int wm = wid & 1, wn = wid >> 1;
    int z = blockIdx.z, b = z / NSPLIT, s = z % NSPLIT;
    Qh += (size_t)b * qBs; Ql += (size_t)b * qBs;
    Kh += (size_t)b * kBs; Kl += (size_t)b * kBs;
    int iBase = blockIdx.y * 128, jBase = blockIdx.x * 128;
    const int chunk = GN / NSPLIT;      // 1024
    int n0 = s * chunk;
    unsigned sb0 = s2u(smem);

    auto stage = [&](int kk, int buf) {
        unsigned base = sb0 + buf * NBUF;
#pragma unroll
        for (int i = 0; i < 8; i++) {
            int c = tid + 256 * i;
            int p = c >> 9, r = (c >> 2) & 127, sg = c & 3;
            const bf16* pl[4] = { Qh, Ql, Kh, Kl };
            int rowBase = (p < 2) ? iBase : jBase;
            const bf16* src = pl[p] + (size_t)(rowBase + r) * GN + n0 + kk + sg * 8;
            cpa16(base + p * 10240 + r * 80 + sg * 16, src);
        }
        cp_commit();
    };

    float acc[4][4][4];
#pragma unroll
    for (int i = 0; i < 4; i++)
#pragma unroll
        for (int j = 0; j < 4; j++)
#pragma unroll
            for (int q = 0; q < 4; q++) acc[i][j][q] = 0.0f;

    unsigned aRow = (unsigned)(wm * 64 + (lane & 15));
    unsigned aKof = (unsigned)((lane >> 4) * 8);
    unsigned bJrow = (unsigned)(wn * 32 + (lane & 7) + ((lane >> 4) & 1) * 8);
    unsigned bKof = (unsigned)(((lane >> 3) & 1) * 8);

    int KT = chunk >> 5;
    stage(0, 0);
    for (int t = 0; t < KT; t++) {
        int cb = t & 1;
        if (t + 1 < KT) {
            stage((t + 1) * 32, cb ^ 1);
            cp_wait1();
        } else {
            cp_wait0();
        }
        __syncthreads();

        const bf16* sQ0 = (const bf16*)(smem + cb * NBUF);
        const bf16* sQ1 = (const bf16*)(smem + cb * NBUF + 10240);
        const bf16* sK0 = (const bf16*)(smem + cb * NBUF + 20480);
        const bf16* sK1 = (const bf16*)(smem + cb * NBUF + 30720);
#pragma unroll
        for (int ks = 0; ks < 32; ks += 16) {
            unsigned ah[4][4], bh[2][4];
#pragma unroll
            for (int mt = 0; mt < 4; mt++)
                ldm4(ah[mt], s2u(&sQ0[(aRow + mt * 16) * 40 + ks + aKof]));
#pragma unroll
            for (int n2 = 0; n2 < 2; n2++)
                ldm4(bh[n2], s2u(&sK0[(bJrow + n2 * 16) * 40 + ks + bKof]));
#pragma unroll
            for (int mt = 0; mt < 4; mt++)
#pragma unroll
                for (int nt = 0; nt < 4; nt++)
                    mma_bf16(acc[mt][nt], ah[mt], bh[nt >> 1][(nt & 1) * 2],
                             bh[nt >> 1][(nt & 1) * 2 + 1]);
            unsigned bl[2][4];
#pragma unroll
            for (int n2 = 0; n2 < 2; n2++)
                ldm4(bl[n2], s2u(&sK1[(bJrow + n2 * 16) * 40 + ks + bKof]));
#pragma unroll
            for (int mt = 0; mt < 4; mt++)
#pragma unroll
                for (int nt = 0; nt < 4; nt++)
                    mma_bf16(acc[mt][nt], ah[mt], bl[nt >> 1][(nt & 1) * 2],
                             bl[nt >> 1][(nt & 1) * 2 + 1]);
            unsigned al[4][4];
#pragma unroll
            for (int mt = 0; mt < 4; mt++)
                ldm4(al[mt], s2u(&sQ1[(aRow + mt * 16) * 40 + ks + aKof]));
#pragma unroll
            for (int mt = 0; mt < 4; mt++)
#pragma unroll
                for (int nt = 0; nt < 4; nt++)
                    mma_bf16(acc[mt][nt], al[mt], bh[nt >> 1][(nt & 1) * 2],
                             bh[nt >> 1][(nt & 1) * 2 + 1]);
        }
        __syncthreads();
    }

    int g = lane >> 2, tg = lane & 3;
#pragma unroll
    for (int mt = 0; mt < 4; mt++) {
#pragma unroll
        for (int nt = 0; nt < 4; nt++) {
            int r0 = iBase + wm * 64 + mt * 16 + g;
            int col = jBase + wn * 32 + nt * 8 + tg * 2;
            float* c = acc[mt][nt];
#pragma unroll
            for (int h2 = 0; h2 < 2; h2++) {
                size_t base = ((size_t)z * 256 + r0 + h2 * 8) * J + col;
                *(float2*)&P[base] = make_float2(c[2 * h2], c[2 * h2 + 1]);
            }
        }
    }
}

__global__ __launch_bounds__(256)
void split_w8(const float* w0, const float* w1, const float* w2, const float* w3,
              const float* w4, const float* w5, const float* w6, const float* w7,
              bf16* __restrict__ H, bf16* __restrict__ L) {
    const float* srcs[8] = { w0, w1, w2, w3, w4, w5, w6, w7 };
    int w = blockIdx.y;
    const float* X = srcs[w];
    int i = blockIdx.x * 256 + threadIdx.x;
    float4 v = ((const float4*)X)[i];
    bf162 h0, l0, h1, l1;
    split2(v.x, v.y, h0, l0);
    split2(v.z, v.w, h1, l1);
    size_t o = (size_t)w * 32768 + 2 * i;
    ((bf162*)H)[o] = h0; ((bf162*)H)[o + 1] = h1;
    ((bf162*)L)[o] = l0; ((bf162*)L)[o + 1] = l1;
}

__global__ __launch_bounds__(256)
void split_arr(const float* __restrict__ X, bf16* __restrict__ H,
               bf16* __restrict__ L, int n4) {
    int i = blockIdx.x * 256 + threadIdx.x;
    if (i < n4) {
        float4 v = ((const float4*)X)[i];
        bf162 h0, l0, h1, l1;
        split2(v.x, v.y, h0, l0);
        split2(v.z, v.w, h1, l1);
        ((bf162*)H)[2 * i] = h0; ((bf162*)H)[2 * i + 1] = h1;
        ((bf162*)L)[2 * i] = l0; ((bf162*)L)[2 * i + 1] = l1;
    }
}

// two-pass instance norm (fastest measured variant)
__global__ __launch_bounds__(256)
void inorm_split(const float* __restrict__ X, bf16* __restrict__ H, bf16* __restrict__ L,
                 const float* __restrict__ gamma, const float* __restrict__ beta) {
    __shared__ float sb[256];
    int row = blockIdx.x, cch = row & (ECH - 1);
    const float4* xr = (const float4*)(X + (size_t)row * GN);
    bf162* hr = (bf162*)(H + (size_t)row * GN);
    bf162* lr = (bf162*)(L + (size_t)row * GN);
    float s = 0.f, ss = 0.f;
    for (int i = threadIdx.x; i < GN / 4; i += 256) {
        float4 v = xr[i];
        s += v.x + v.y + v.z + v.w;
        ss += v.x * v.x + v.y * v.y + v.z * v.z + v.w * v.w;
    }
    float tot = brsum(s, sb), tot2 = brsum(ss, sb);
    const float inv = 1.0f / (float)GN;
    float mu = tot * inv, var = tot2 * inv - mu * mu;
    float rstd = rsqrtf(var + 1e-5f);
    float a = rstd * gamma[cch], bb = beta[cch] - mu * a;
    for (int i = threadIdx.x; i < GN / 4; i += 256) {
        float4 v = xr[i];
        float y0 = v.x * a + bb, y1 = v.y * a + bb;
        float y2 = v.z * a + bb, y3 = v.w * a + bb;
        bf162 h0, l0, h1, l1;
        split2(y0, y1, h0, l0);
        split2(y2, y3, h1, l1);
        hr[2 * i] = h0; hr[2 * i + 1] = h1;
        lr[2 * i] = l0; lr[2 * i + 1] = l1;
    }
}

__global__ __launch_bounds__(256)
void softmax_split(const float* __restrict__ P, bf16* __restrict__ SH,
                   bf16* __restrict__ SL, int J, float scale) {
    __shared__ float rowbuf[512];
    __shared__ float sb[256];
    int row = blockIdx.x, b = row >> 8, i = row & 255, tid = threadIdx.x;
    for (int j = tid; j < J; j += 256) {
        float v = 0.f;
#pragma unroll
        for (int s = 0; s < NSPLIT; s++)
            v += P[(((size_t)(b * NSPLIT + s) * 256) + i) * J + j];
        rowbuf[j] = v * scale;
    }
    __syncthreads();
    float ls = 0.f;
    for (int j = tid; j < J; j += 256) ls += rowbuf[j];
    float mean = brsum(ls, sb) / (float)J;
    float lv = 0.f;
    for (int j = tid; j < J; j += 256) { float d = rowbuf[j] - mean; lv += d * d; }
    float rstd = rsqrtf(brsum(lv, sb) / (float)J + 1e-5f);
    float lm = -1e30f;
    for (int j = tid; j < J; j += 256) {
        float tt = (rowbuf[j] - mean) * rstd;
        rowbuf[j] = tt;
        lm = fmaxf(lm, tt);
    }
    float mx = brmax(lm, sb);
    float le = 0.f;
    for (int j = tid; j < J; j += 256) {
        float e = expf(rowbuf[j] - mx);
        rowbuf[j] = e;
        le += e;
    }
    float rden = 1.0f / brsum(le, sb);
    size_t ob = ((size_t)b * 256 + i) * J;
    for (int j = tid; j < J; j += 256) {
        float y = rowbuf[j] * rden;
        bf16 h = __float2bfloat16_rn(y);
        SH[ob + j] = h;
        SL[ob + j] = __float2bfloat16_rn(y - __bfloat162float(h));
    }
}

extern "C" void kernel_launch(void* const* d_in, const int* in_sizes, int n_in,
                              void* d_out, int out_size) {
    const float* feat = (const float*)d_in[0];
    const float* kv   = (const float*)d_in[1];
    const float* ag = (const float*)d_in[10];
    const float* ab = (const float*)d_in[11];
    const float* eg = (const float*)d_in[12];
    const float* eb = (const float*)d_in[13];
    float* out = (float*)d_out;

    float *emb, *pre, *pu, *plw;
    bf16 *fh, *fl, *nh, *nl, *qkvh, *qkvl, *th, *tl;
    bf16 *kvh, *kvl, *suh, *sul, *slh, *sll, *wh, *wl;
    cudaGetSymbolAddress((void**)&emb, g_emb);
    cudaGetSymbolAddress((void**)&pre, g_pre);
    cudaGetSymbolAddress((void**)&pu, g_pu);
    cudaGetSymbolAddress((void**)&plw, g_plw);
    cudaGetSymbolAddress((void**)&fh, g_fh);   cudaGetSymbolAddress((void**)&fl, g_fl);
    cudaGetSymbolAddress((void**)&nh, g_nh);   cudaGetSymbolAddress((void**)&nl, g_nl);
    cudaGetSymbolAddress((void**)&qkvh, g_qkvh); cudaGetSymbolAddress((void**)&qkvl, g_qkvl);
    cudaGetSymbolAddress((void**)&th, g_th);   cudaGetSymbolAddress((void**)&tl, g_tl);
    cudaGetSymbolAddress((void**)&kvh, g_kvh); cudaGetSymbolAddress((void**)&kvl, g_kvl);
    cudaGetSymbolAddress((void**)&suh, g_suh); cudaGetSymbolAddress((void**)&sul, g_sul);
    cudaGetSymbolAddress((void**)&slh, g_slh); cudaGetSymbolAddress((void**)&sll, g_sll);
    cudaGetSymbolAddress((void**)&wh, g_wh);   cudaGetSymbolAddress((void**)&wl, g_wl);

    bf16 *qh = qkvh, *ql = qkvl;
    bf16 *kh = qkvh + TOT4, *kl = qkvl + TOT4;
    bf16 *vh = qkvh + 2 * TOT4, *vl = qkvl + 2 * TOT4;

    cudaFuncSetAttribute(gemm_cp, cudaFuncAttributeMaxDynamicSharedMemorySize, CSMEM3);
    cudaFuncSetAttribute(gemmnt_cp, cudaFuncAttributeMaxDynamicSharedMemorySize, NSMEM);

    const float scale = 1.0f / 128.0f;
    dim3 blk(256);
    dim3 g8(GN / 128, 2, 8);
    dim3 g4(GN / 128, 2, 4);

    // #1 weights (one launch)
    split_w8<<<dim3(64, 8), blk>>>((const float*)d_in[2], (const float*)d_in[3],
                                   (const float*)d_in[4], (const float*)d_in[5],
                                   (const float*)d_in[6], (const float*)d_in[7],
                                   (const float*)d_in[8], (const float*)d_in[9], wh, wl);
    // #2 feat, #3 kv
    split_arr<<<32768, blk>>>(feat, fh, fl, 8388608);
    split_arr<<<8192, blk>>>(kv, kvh, kvl, 2097152);
    // #4 emb = gelu(w_in @ feat)
    gemm_cp<<<g8, blk, CSMEM3>>>(wh, wl, 0, fh, fl, BSTR, emb, nullptr, nullptr,
                                 BSTR, 0, nullptr, 256, 1 | 8);
    // #5 nrm planes
    inorm_split<<<NB * ECH, blk>>>(emb, nh, nl, ag, ab);
    // #6 fused QKV (M=768) -> PROFILED
    gemm_cp<<<dim3(GN / 128, 6, 4), blk, CSMEM3>>>(wh + 2 * 65536, wl + 2 * 65536, 0,
                                                   nh + TOT4, nl + TOT4, BSTR,
                                                   nullptr, qkvh, qkvl, BSTR, TOT4,
                                                   nullptr, 256, 4);
    // #7 upper scores (NSPLIT=16 -> 256 CTAs)
    gemmnt_cp<<<dim3(2, 2, HB * NSPLIT), blk, NSMEM>>>(qh, ql, BSTR, kh, kl, BSTR, pu, 256);
    // #8 softmax upper
    softmax_split<<<HB * 256, blk>>>(pu, suh, sul, 256, scale);
    // #9 upper t = su @ v -> t batches 4..7
    gemm_cp<<<g4, blk, CSMEM3>>>(suh, sul, 65536, vh, vl, BSTR, nullptr,
                                 th + TOT4, tl + TOT4, BSTR, 0, nullptr, 256, 4);
    // #10 lower Ql (overwrites q planes; safe: #7 already consumed them)
    gemm_cp<<<g4, blk, CSMEM3>>>(wh + 6 * 65536, wl + 6 * 65536, 0, nh, nl, BSTR,
                                 nullptr, qh, ql, BSTR, 0, nullptr, 256, 4);
    // #11 lower scores (kv shared; 512 CTAs)
    gemmnt_cp<<<dim3(4, 2, HB * NSPLIT), blk, NSMEM>>>(qh, ql, BSTR, kvh, kvl, 0, plw, 512);
    // #12 softmax lower (J=512)
    softmax_split<<<HB * 256, blk>>>(plw, slh, sll, 512, scale);
    // #13 lower ca = sl @ kv (K=512) -> t batches 0..3
    gemm_cp<<<g4, blk, CSMEM3>>>(slh, sll, 131072, kvh, kvl, 0, nullptr, th, tl,
                                 BSTR, 0, nullptr, 512, 4);
    // #14 MERGED pre = W_o @ t + emb (b<4: wo_ca, b>=4: wo_sa), all 8 batches
    gemm_cp<<<g8, blk, CSMEM3>>>(wh, wl, 0, th, tl, BSTR, pre, nullptr, nullptr,
                                 BSTR, 0, emb, 256, 2 | 8 | 16);
    // #15 nrm2
    inorm_split<<<NB * ECH, blk>>>(pre, nh, nl, eg, eb);
    // #16 out = gelu(w_out @ nrm2)
    gemm_cp<<<g8, blk, CSMEM3>>>(wh + 65536, wl + 65536, 0, nh, nl, BSTR, out,
                                 nullptr, nullptr, BSTR, 0, nullptr, 256, 1 | 8);
}

// round 12
// speedup vs baseline: 1.0155x; 1.0155x over previous
#include <cuda_runtime.h>
#include <cuda_bf16.h>
#include <math.h>

#define GN 16384
#define ECH 256
#define NB 8
#define HB 4
static const size_t BSTR = (size_t)ECH * GN;
static const size_t TOT4 = (size_t)HB * BSTR;
typedef __nv_bfloat16 bf16;
typedef __nv_bfloat162 bf162;

__device__ float g_emb[33554432];
__device__ float g_pre[33554432];
__device__ float g_pu[HB * 16 * 256 * 256];     // upper partials (nsplit=16)
__device__ float g_plw[HB * 8 * 256 * 512];     // lower partials (nsplit=8)
__device__ bf16 g_fh[33554432], g_fl[33554432];
__device__ bf16 g_nh[33554432], g_nl[33554432];
__device__ bf16 g_qkvh[50331648], g_qkvl[50331648];
__device__ bf16 g_th[16777216], g_tl[16777216];
__device__ bf16 g_kvh[8388608], g_kvl[8388608];
__device__ bf16 g_suh[1048576], g_sul[1048576];
__device__ bf16 g_slh[1048576], g_sll[1048576];
__device__ bf16 g_wh[524288], g_wl[524288];

__device__ __forceinline__ unsigned s2u(const void* p) {
    return (unsigned)__cvta_generic_to_shared(p);
}
__device__ __forceinline__ void cpa16(unsigned dst, const void* src) {
    asm volatile("cp.async.cg.shared.global [%0], [%1], 16;" :: "r"(dst), "l"(src));
}
__device__ __forceinline__ void cp_commit() { asm volatile("cp.async.commit_group;"); }
__device__ __forceinline__ void cp_wait0() { asm volatile("cp.async.wait_group 0;" ::: "memory"); }
__device__ __forceinline__ void cp_wait1() { asm volatile("cp.async.wait_group 1;" ::: "memory"); }

__device__ __forceinline__ void ldm4(unsigned* r, unsigned a) {
    asm volatile("ldmatrix.sync.aligned.m8n8.x4.shared.b16 {%0,%1,%2,%3}, [%4];"
                 : "=r"(r[0]), "=r"(r[1]), "=r"(r[2]), "=r"(r[3]) : "r"(a));
}
__device__ __forceinline__ void ldm4t(unsigned* r, unsigned a) {
    asm volatile("ldmatrix.sync.aligned.m8n8.x4.trans.shared.b16 {%0,%1,%2,%3}, [%4];"
                 : "=r"(r[0]), "=r"(r[1]), "=r"(r[2]), "=r"(r[3]) : "r"(a));
}
__device__ __forceinline__ void mma_bf16(float* c, const unsigned* a, unsigned b0, unsigned b1) {
    asm volatile(
        "mma.sync.aligned.m16n8k16.row.col.f32.bf16.bf16.f32 "
        "{%0,%1,%2,%3},{%4,%5,%6,%7},{%8,%9},{%0,%1,%2,%3};"
        : "+f"(c[0]), "+f"(c[1]), "+f"(c[2]), "+f"(c[3])
        : "r"(a[0]), "r"(a[1]), "r"(a[2]), "r"(a[3]), "r"(b0), "r"(b1));
}
__device__ __forceinline__ void split2(float a, float b, bf162& h, bf162& l) {
    h = __floats2bfloat162_rn(a, b);
    float2 hf = __bfloat1622float2(h);
    l = __floats2bfloat162_rn(a - hf.x, b - hf.y);
}
__device__ __forceinline__ float gelu_exact(float x) {
    return 0.5f * x * (1.0f + erff(x * 0.70710678118654752f));
}
__device__ __forceinline__ float brsum(float v, float* sb) {
    int t = threadIdx.x;
    sb[t] = v; __syncthreads();
    for (int s = 128; s > 0; s >>= 1) { if (t < s) sb[t] += sb[t + s]; __syncthreads(); }
    float r = sb[0]; __syncthreads(); return r;
}
__device__ __forceinline__ float brmax(float v, float* sb) {
    int t = threadIdx.x;
    sb[t] = v; __syncthreads();
    for (int s = 128; s > 0; s >>= 1) { if (t < s) sb[t] = fmaxf(sb[t], sb[t + s]); __syncthreads(); }
    float r = sb[0]; __syncthreads(); return r;
}

#define CBUF 37888
#define CSMEM3 113664          // 3 buffers, single-sync pipeline
#define NBUF 40960
#define NSMEM 81920

// conv1x1 GEMM: C[b](M x GN) = A[b](M x K) @ B[b](K x GN); M = 128*gridDim.y
// epi bits: 1 gelu, 2 +R, 4 split-out, 8 fp32-out. Row-group stride oGrp.
__global__ __launch_bounds__(256, 2)
void gemm_cp(const bf16* __restrict__ Ah, const bf16* __restrict__ Al, size_t aBs,
             const bf16* __restrict__ Bh, const bf16* __restrict__ Bl, size_t bBs,
             float* __restrict__ C, bf16* __restrict__ Ch, bf16* __restrict__ Cl,
             size_t cBs, size_t oGrp, const float* __restrict__ R,
             int K, int epi) {
    extern __shared__ char smem[];
    int tid = threadIdx.x, wid = tid >> 5, lane = tid & 31;
    int wm = wid & 1, wn = wid >> 1;
    int oBase = blockIdx.y * 128, nBase = blockIdx.x * 128;
    int b = blockIdx.z;
    Ah += (size_t)b * aBs; Al += (size_t)b * aBs;
    Bh += (size_t)b * bBs; Bl += (size_t)b * bBs;

    unsigned sb0 = s2u(smem);
    auto stage = [&](int kk, int buf) {
        unsigned base = sb0 + buf * CBUF;
#pragma unroll
        for (int i = 0; i < 8; i++) {
            int c = tid + 256 * i;
            if (i < 4) {
                int p = c >> 9, r = (c >> 2) & 127, s = c & 3;
                const bf16* src = (p ? Al : Ah) + (size_t)(oBase + r) * K + kk + s * 8;
                cpa16(base + p * 10240 + r * 80 + s * 16, src);
            } else {
                int c2 = c - 1024;
                int p = c2 >> 9, r = (c2 >> 4) & 31, s = c2 & 15;
                const bf16* src = (p ? Bl : Bh) + (size_t)(kk + r) * GN + nBase + s * 8;
                cpa16(base + 20480 + p * 8704 + r * 272 + s * 16, src);
            }
        }
        cp_commit();
    };

    float acc[4][4][4];
#pragma unroll
    for (int i = 0; i < 4; i++)
#pragma unroll
        for (int j = 0; j < 4; j++)
#pragma unroll
            for (int q = 0; q < 4; q++) acc[i][j][q] = 0.0f;

    unsigned aRow = (unsigned)(wm * 64 + (lane & 15));
    unsigned aKof = (unsigned)((lane >> 4) * 8);
    unsigned bKrow = (unsigned)((lane & 7) + ((lane >> 3) & 1) * 8);
    unsigned bNcol = (unsigned)(wn * 32 + ((lane >> 4) & 1) * 8);

    int KT = K >> 5;
    stage(0, 0);
    if (KT > 1) stage(32, 1);
    int buf = 0;
    for (int t = 0; t < KT; t++) {
        if (t + 2 < KT) cp_wait1(); else cp_wait0();
        __syncthreads();
        if (t + 2 < KT) {
            int nb = buf + 2; if (nb >= 3) nb -= 3;
            stage((t + 2) * 32, nb);
        }

        const bf16* sA0 = (const bf16*)(smem + buf * CBUF);
        const bf16* sA1 = (const bf16*)(smem + buf * CBUF + 10240);
        const bf16* sB0 = (const bf16*)(smem + buf * CBUF + 20480);
        const bf16* sB1 = (const bf16*)(smem + buf * CBUF + 29184);
#pragma unroll
        for (int ks = 0; ks < 32; ks += 16) {
            unsigned ah[4][4], bh[2][4];
#pragma unroll
            for (int mt = 0; mt < 4; mt++)
                ldm4(ah[mt], s2u(&sA0[(aRow + mt * 16) * 40 + ks + aKof]));
#pragma unroll
            for (int n2 = 0; n2 < 2; n2++)
                ldm4t(bh[n2], s2u(&sB0[(bKrow + ks) * 136 + bNcol + n2 * 16]));
#pragma unroll
            for (int mt = 0; mt < 4; mt++)
#pragma unroll
                for (int nt = 0; nt < 4; nt++)
                    mma_bf16(acc[mt][nt], ah[mt], bh[nt >> 1][(nt & 1) * 2],
                             bh[nt >> 1][(nt & 1) * 2 + 1]);
            unsigned bl[2][4];
#pragma unroll
            for (int n2 = 0; n2 < 2; n2++)
                ldm4t(bl[n2], s2u(&sB1[(bKrow + ks) * 136 + bNcol + n2 * 16]));
#pragma unroll
            for (int mt = 0; mt < 4; mt++)
#pragma unroll
                for (int nt = 0; nt < 4; nt++)
                    mma_bf16(acc[mt][nt], ah[mt], bl[nt >> 1][(nt & 1) * 2],
                             bl[nt >> 1][(nt & 1) * 2 + 1]);
            unsigned al[4][4];
#pragma unroll
            for (int mt = 0; mt < 4; mt++)
                ldm4(al[mt], s2u(&sA1[(aRow + mt * 16) * 40 + ks + aKof]));
#pragma unroll
            for (int mt = 0; mt < 4; mt++)
#pragma unroll
                for (int nt = 0; nt < 4; nt++)
                    mma_bf16(acc[mt][nt], al[mt], bh[nt >> 1][(nt & 1) * 2],
                             bh[nt >> 1][(nt & 1) * 2 + 1]);
        }
        buf++; if (buf >= 3) buf -= 3;
    }

    int g = lane >> 2, tg = lane & 3;
#pragma unroll
    for (int mt = 0; mt < 4; mt++) {
#pragma unroll
        for (int nt = 0; nt < 4; nt++) {
            int r0 = oBase + wm * 64 + mt * 16 + g;
            int col = nBase + wn * 32 + nt * 8 + tg * 2;
            float* c = acc[mt][nt];
#pragma unroll
            for (int h2 = 0; h2 < 2; h2++) {
                int rr = r0 + h2 * 8;
                size_t base = (size_t)(rr >> 8) * oGrp + (size_t)b * cBs
                            + (size_t)(rr & 255) * GN + col;
                float o0 = c[2 * h2], o1 = c[2 * h2 + 1];
                if (epi & 2) {
                    float2 rv = *(const float2*)&R[base];
                    o0 += rv.x; o1 += rv.y;
                }
                if (epi & 1) { o0 = gelu_exact(o0); o1 = gelu_exact(o1); }
                if (epi & 8) *(float2*)&C[base] = make_float2(o0, o1);
                if (epi & 4) {
                    bf162 h, l;
                    split2(o0, o1, h, l);
                    *(bf162*)&Ch[base] = h;
                    *(bf162*)&Cl[base] = l;
                }
            }
        }
    }
}

// NT score GEMM, per-launch nsplit: P[z][i][j] = sum_{n in chunk} Q[i][n] K[j][n]
__global__ __launch_bounds__(256, 2)
void gemmnt_cp(const bf16* __restrict__ Qh, const bf16* __restrict__ Ql, size_t qBs,
               const bf16* __restrict__ Kh, const bf16* __restrict__ Kl, size_t kBs,
               float* __restrict__ P, int J, int nsplit) {
    extern __shared__ char smem[];
    int tid = threadIdx.x, wid = tid >> 5, lane = tid & 31;
    int wm = wid & 1, wn = wid >> 1;
    int z = blockIdx.z, b = z / nsplit, s = z % nsplit;
    Qh += (size_t)b * qBs; Ql += (size_t)b * qBs;
    Kh += (size_t)b * kBs; Kl += (size_t)b * kBs;
    int iBase = blockIdx.y * 128, jBase = blockIdx.x * 128;
    const int chunk = GN / nsplit;
    int n0 = s * chunk;
    unsigned sb0 = s2u(smem);

    auto stage = [&](int kk, int buf) {
        unsigned base = sb0 + buf * NBUF;
#pragma unroll
        for (int i = 0; i < 8; i++) {
            int c = tid + 256 * i;
            int p = c >> 9, r = (c >> 2) & 127, sg = c & 3;
            const bf16* pl[4] = { Qh, Ql, Kh, Kl };
            int rowBase = (p < 2) ? iBase : jBase;
            const bf16* src = pl[p] + (size_t)(rowBase + r) * GN + n0 + kk + sg * 8;
            cpa16(base + p * 10240 + r * 80 + sg * 16, src);
        }
        cp_commit();
    };

    float acc[4][4][4];
#pragma unroll
    for (int i = 0; i < 4; i++)
#pragma unroll
        for (int j = 0; j < 4; j++)
#pragma unroll
            for (int q = 0; q < 4; q++) acc[i][j][q] = 0.0f;

    unsigned aRow = (unsigned)(wm * 64 + (lane & 15));
    unsigned aKof = (unsigned)((lane >> 4) * 8);
    unsigned bJrow = (unsigned)(wn * 32 + (lane & 7) + ((lane >> 4) & 1) * 8);
    unsigned bKof = (unsigned)(((lane >> 3) & 1) * 8);

    int KT = chunk >> 5;
    stage(0, 0);
    for (int t = 0; t < KT; t++) {
        int cb = t & 1;
        if (t + 1 < KT) {
            stage((t + 1) * 32, cb ^ 1);
            cp_wait1();
        } else {
            cp_wait0();
        }
        __syncthreads();

        const bf16* sQ0 = (const bf16*)(smem + cb * NBUF);
        const bf16* sQ1 = (const bf16*)(smem + cb * NBUF + 10240);
        const bf16* sK0 = (const bf16*)(smem + cb * NBUF + 20480);
        const bf16* sK1 = (const bf16*)(smem + cb * NBUF + 30720);
#pragma unroll
        for (int ks = 0; ks < 32; ks += 16) {
            unsigned ah[4][4], bh[2][4];
#pragma unroll
            for (int mt = 0; mt < 4; mt++)
                ldm4(ah[mt], s2u(&sQ0[(aRow + mt * 16) * 40 + ks + aKof]));
#pragma unroll
            for (int n2 = 0; n2 < 2; n2++)
                ldm4(bh[n2], s2u(&sK0[(bJrow + n2 * 16) * 40 + ks + bKof]));
#pragma unroll
            for (int mt = 0; mt < 4; mt++)
#pragma unroll
                for (int nt = 0; nt < 4; nt++)
                    mma_bf16(acc[mt][nt], ah[mt], bh[nt >> 1][(nt & 1) * 2],
                             bh[nt >> 1][(nt & 1) * 2 + 1]);
            unsigned bl[2][4];
#pragma unroll
            for (int n2 = 0; n2 < 2; n2++)
                ldm4(bl[n2], s2u(&sK1[(bJrow + n2 * 16) * 40 + ks + bKof]));
#pragma unroll
            for (int mt = 0; mt < 4; mt++)
#pragma unroll
                for (int nt = 0; nt < 4; nt++)
                    mma_bf16(acc[mt][nt], ah[mt], bl[nt >> 1][(nt & 1) * 2],
                             bl[nt >> 1][(nt & 1) * 2 + 1]);
            unsigned al[4][4];
#pragma unroll
            for (int mt = 0; mt < 4; mt++)
                ldm4(al[mt], s2u(&sQ1[(aRow + mt * 16) * 40 + ks + aKof]));
#pragma unroll
            for (int mt = 0; mt < 4; mt++)
#pragma unroll
                for (int nt = 0; nt < 4; nt++)
                    mma_bf16(acc[mt][nt], al[mt], bh[nt >> 1][(nt & 1) * 2],
                             bh[nt >> 1][(nt & 1) * 2 + 1]);
        }
        __syncthreads();
    }

    int g = lane >> 2, tg = lane & 3;
#pragma unroll
    for (int mt = 0; mt < 4; mt++) {
#pragma unroll
        for (int nt = 0; nt < 4; nt++) {
            int r0 = iBase + wm * 64 + mt * 16 + g;
            int col = jBase + wn * 32 + nt * 8 + tg * 2;
            float* c = acc[mt][nt];
#pragma unroll
            for (int h2 = 0; h2 < 2; h2++) {
                size_t base = ((size_t)z * 256 + r0 + h2 * 8) * J + col;
                *(float2*)&P[base] = make_float2(c[2 * h2], c[2 * h2 + 1]);
            }
        }
    }
}

__global__ __launch_bounds__(256)
void split_w8(const float* w0, const float* w1, const float* w2, const float* w3,
              const float* w4, const float* w5, const float* w6, const float* w7,
              bf16* __restrict__ H, bf16* __restrict__ L) {
    const float* srcs[8] = { w0, w1, w2, w3, w4, w5, w6, w7 };
    int w = blockIdx.y;
    const float* X = srcs[w];
    int i = blockIdx.x * 256 + threadIdx.x;
    float4 v = ((const float4*)X)[i];
    bf162 h0, l0, h1, l1;
    split2(v.x, v.y, h0, l0);
    split2(v.z, v.w, h1, l1);
    size_t o = (size_t)w * 32768 + 2 * i;
    ((bf162*)H)[o] = h0; ((bf162*)H)[o + 1] = h1;
    ((bf162*)L)[o] = l0; ((bf162*)L)[o + 1] = l1;
}

__global__ __launch_bounds__(256)
void split_arr(const float* __restrict__ X, bf16* __restrict__ H,
               bf16* __restrict__ L, int n4) {
    int i = blockIdx.x * 256 + threadIdx.x;
    if (i < n4) {
        float4 v = ((const float4*)X)[i];
        bf162 h0, l0, h1, l1;
        split2(v.x, v.y, h0, l0);
        split2(v.z, v.w, h1, l1);
        ((bf162*)H)[2 * i] = h0; ((bf162*)H)[2 * i + 1] = h1;
        ((bf162*)L)[2 * i] = l0; ((bf162*)L)[2 * i + 1] = l1;
    }
}

// two-pass instance norm (fastest measured variant)
__global__ __launch_bounds__(256)
void inorm_split(const float* __restrict__ X, bf16* __restrict__ H, bf16* __restrict__ L,
                 const float* __restrict__ gamma, const float* __restrict__ beta) {
    __shared__ float sb[256];
    int row = blockIdx.x, cch = row & (ECH - 1);
    const float4* xr = (const float4*)(X + (size_t)row * GN);
    bf162* hr = (bf162*)(H + (size_t)row * GN);
    bf162* lr = (bf162*)(L + (size_t)row * GN);
    float s = 0.f, ss = 0.f;
    for (int i = threadIdx.x; i < GN / 4; i += 256) {
        float4 v = xr[i];
        s += v.x + v.y + v.z + v.w;
        ss += v.x * v.x + v.y * v.y + v.z * v.z + v.w * v.w;
    }
    float tot = brsum(s, sb), tot2 = brsum(ss, sb);
    const float inv = 1.0f / (float)GN;
    float mu = tot * inv, var = tot2 * inv - mu * mu;
    float rstd = rsqrtf(var + 1e-5f);
    float a = rstd * gamma[cch], bb = beta[cch] - mu * a;
    for (int i = threadIdx.x; i < GN / 4; i += 256) {
        float4 v = xr[i];
        float y0 = v.x * a + bb, y1 = v.y * a + bb;
        float y2 = v.z * a + bb, y3 = v.w * a + bb;
        bf162 h0, l0, h1, l1;
        split2(y0, y1, h0, l0);
        split2(y2, y3, h1, l1);
        hr[2 * i] = h0; hr[2 * i + 1] = h1;
        lr[2 * i] = l0; lr[2 * i + 1] = l1;
    }
}

__global__ __launch_bounds__(256)
void softmax_split(const float* __restrict__ P, bf16* __restrict__ SH,
                   bf16* __restrict__ SL, int J, float scale, int nsplit) {
    __shared__ float rowbuf[512];
    __shared__ float sb[256];
    int row = blockIdx.x, b = row >> 8, i = row & 255, tid = threadIdx.x;
    for (int j = tid; j < J; j += 256) {
        float v = 0.f;
        for (int s = 0; s < nsplit; s++)
            v += P[(((size_t)(b * nsplit + s) * 256) + i) * J + j];
        rowbuf[j] = v * scale;
    }
    __syncthreads();
    float ls = 0.f;
    for (int j = tid; j < J; j += 256) ls += rowbuf[j];
    float mean = brsum(ls, sb) / (float)J;
    float lv = 0.f;
    for (int j = tid; j < J; j += 256) { float d = rowbuf[j] - mean; lv += d * d; }
    float rstd = rsqrtf(brsum(lv, sb) / (float)J + 1e-5f);
    float lm = -1e30f;
    for (int j = tid; j < J; j += 256) {
        float tt = (rowbuf[j] - mean) * rstd;
        rowbuf[j] = tt;
        lm = fmaxf(lm, tt);
    }
    float mx = brmax(lm, sb);
    float le = 0.f;
    for (int j = tid; j < J; j += 256) {
        float e = expf(rowbuf[j] - mx);
        rowbuf[j] = e;
        le += e;
    }
    float rden = 1.0f / brsum(le, sb);
    size_t ob = ((size_t)b * 256 + i) * J;
    for (int j = tid; j < J; j += 256) {
        float y = rowbuf[j] * rden;
        bf16 h = __float2bfloat16_rn(y);
        SH[ob + j] = h;
        SL[ob + j] = __float2bfloat16_rn(y - __bfloat162float(h));
    }
}

extern "C" void kernel_launch(void* const* d_in, const int* in_sizes, int n_in,
                              void* d_out, int out_size) {
    const float* feat = (const float*)d_in[0];
    const float* kv   = (const float*)d_in[1];
    const float* ag = (const float*)d_in[10];
    const float* ab = (const float*)d_in[11];
    const float* eg = (const float*)d_in[12];
    const float* eb = (const float*)d_in[13];
    float* out = (float*)d_out;

    float *emb, *pre, *pu, *plw;
    bf16 *fh, *fl, *nh, *nl, *qkvh, *qkvl, *th, *tl;
    bf16 *kvh, *kvl, *suh, *sul, *slh, *sll, *wh, *wl;
    cudaGetSymbolAddress((void**)&emb, g_emb);
    cudaGetSymbolAddress((void**)&pre, g_pre);
    cudaGetSymbolAddress((void**)&pu, g_pu);
    cudaGetSymbolAddress((void**)&plw, g_plw);
    cudaGetSymbolAddress((void**)&fh, g_fh);   cudaGetSymbolAddress((void**)&fl, g_fl);
    cudaGetSymbolAddress((void**)&nh, g_nh);   cudaGetSymbolAddress((void**)&nl, g_nl);
    cudaGetSymbolAddress((void**)&qkvh, g_qkvh); cudaGetSymbolAddress((void**)&qkvl, g_qkvl);
    cudaGetSymbolAddress((void**)&th, g_th);   cudaGetSymbolAddress((void**)&tl, g_tl);
    cudaGetSymbolAddress((void**)&kvh, g_kvh); cudaGetSymbolAddress((void**)&kvl, g_kvl);
    cudaGetSymbolAddress((void**)&suh, g_suh); cudaGetSymbolAddress((void**)&sul, g_sul);
    cudaGetSymbolAddress((void**)&slh, g_slh); cudaGetSymbolAddress((void**)&sll, g_sll);
    cudaGetSymbolAddress((void**)&wh, g_wh);   cudaGetSymbolAddress((void**)&wl, g_wl);

    bf16 *qh = qkvh, *ql = qkvl;
    bf16 *kh = qkvh + TOT4, *kl = qkvl + TOT4;
    bf16 *vh = qkvh + 2 * TOT4, *vl = qkvl + 2 * TOT4;

    cudaFuncSetAttribute(gemm_cp, cudaFuncAttributeMaxDynamicSharedMemorySize, CSMEM3);
    cudaFuncSetAttribute(gemmnt_cp, cudaFuncAttributeMaxDynamicSharedMemorySize, NSMEM);

    const float scale = 1.0f / 128.0f;
    dim3 blk(256);
    dim3 g8(GN / 128, 2, 8);
    dim3 g4(GN / 128, 2, 4);

    // #1 weights (one launch)
    split_w8<<<dim3(64, 8), blk>>>((const float*)d_in[2], (const float*)d_in[3],
                                   (const float*)d_in[4], (const float*)d_in[5],
                                   (const float*)d_in[6], (const float*)d_in[7],
                                   (const float*)d_in[8], (const float*)d_in[9], wh, wl);
    // #2 feat, #3 kv
    split_arr<<<32768, blk>>>(feat, fh, fl, 8388608);
    split_arr<<<8192, blk>>>(kv, kvh, kvl, 2097152);
    // #4 emb = gelu(w_in @ feat)
    gemm_cp<<<g8, blk, CSMEM3>>>(wh, wl, 0, fh, fl, BSTR, emb, nullptr, nullptr,
                                 BSTR, 0, nullptr, 256, 1 | 8);
    // #5 nrm planes
    inorm_split<<<NB * ECH, blk>>>(emb, nh, nl, ag, ab);
    // #6 fused QKV (M=768) -> PROFILED
    gemm_cp<<<dim3(GN / 128, 6, 4), blk, CSMEM3>>>(wh + 2 * 65536, wl + 2 * 65536, 0,
                                                   nh + TOT4, nl + TOT4, BSTR,
                                                   nullptr, qkvh, qkvl, BSTR, TOT4,
                                                   nullptr, 256, 4);
    // #7 upper scores: nsplit=16 -> 256 CTAs (fills chip)
    gemmnt_cp<<<dim3(2, 2, HB * 16), blk, NSMEM>>>(qh, ql, BSTR, kh, kl, BSTR,
                                                   pu, 256, 16);
    // #8 softmax upper (nsplit=16)
    softmax_split<<<HB * 256, blk>>>(pu, suh, sul, 256, scale, 16);
    // #9 upper t = su @ v (A per-batch)
    gemm_cp<<<g4, blk, CSMEM3>>>(suh, sul, 65536, vh, vl, BSTR, nullptr, th, tl,
                                 BSTR, 0, nullptr, 256, 4);
    // #10 pre_u = wo_sa @ t + emb_u
    gemm_cp<<<g4, blk, CSMEM3>>>(wh + 5 * 65536, wl + 5 * 65536, 0, th, tl, BSTR,
                                 pre + TOT4, nullptr, nullptr, BSTR, 0,
                                 emb + TOT4, 256, 2 | 8);
    // #11 lower Ql
    gemm_cp<<<g4, blk, CSMEM3>>>(wh + 6 * 65536, wl + 6 * 65536, 0, nh, nl, BSTR,
                                 nullptr, qh, ql, BSTR, 0, nullptr, 256, 4);
    // #12 lower scores: nsplit=8 -> 256 CTAs (kv shared)
    gemmnt_cp<<<dim3(4, 2, HB * 8), blk, NSMEM>>>(qh, ql, BSTR, kvh, kvl, 0,
                                                  plw, 512, 8);
    // #13 softmax lower (J=512, nsplit=8)
    softmax_split<<<HB * 256, blk>>>(plw, slh, sll, 512, scale, 8);
    // #14 ca = sl @ kv (K=512, A per-batch)
    gemm_cp<<<g4, blk, CSMEM3>>>(slh, sll, 131072, kvh, kvl, 0, nullptr, th, tl,
                                 BSTR, 0, nullptr, 512, 4);
    // #15 pre_l = wo_ca @ ca + emb_l
    gemm_cp<<<g4, blk, CSMEM3>>>(wh + 7 * 65536, wl + 7 * 65536, 0, th, tl, BSTR,
                                 pre, nullptr, nullptr, BSTR, 0, emb, 256, 2 | 8);
    // #16 nrm2
    inorm_split<<<NB * ECH, blk>>>(pre, nh, nl, eg, eb);
    // #17 out = gelu(w_out @ nrm2)
    gemm_cp<<<g8, blk, CSMEM3>>>(wh + 65536, wl + 65536, 0, nh, nl, BSTR, out,
                                 nullptr, nullptr, BSTR, 0, nullptr, 256, 1 | 8);
}

// round 13
// speedup vs baseline: 1.3438x; 1.3233x over previous
#include <cuda_runtime.h>
#include <cuda_fp16.h>
#include <math.h>

#define GN 16384
#define ECH 256
#define NB 8
#define HB 4
static const size_t BSTR = (size_t)ECH * GN;
static const size_t TOT4 = (size_t)HB * BSTR;
typedef __half2 h2;

__device__ float g_emb[33554432];
__device__ float g_pre[33554432];
__device__ float g_pu[HB * 16 * 256 * 256];     // upper partials (nsplit=16)
__device__ float g_plw[HB * 8 * 256 * 512];     // lower partials (nsplit=8)
__device__ __half g_fh[33554432];               // feat hi (B-only)
__device__ __half g_nh[33554432];               // norm hi (B-only)
__device__ __half g_qkvh[50331648], g_qkvl[50331648]; // q needs lo; k/v lo unused
__device__ __half g_th[16777216];               // t hi (B-only)
__device__ __half g_kvh[8388608];               // kv hi (B-only)
__device__ __half g_suh[1048576], g_sul[1048576];
__device__ __half g_slh[1048576], g_sll[1048576];
__device__ __half g_wh[524288], g_wl[524288];   // 8 x 65536 weight slots

__device__ __forceinline__ unsigned s2u(const void* p) {
    return (unsigned)__cvta_generic_to_shared(p);
}
__device__ __forceinline__ void cpa16(unsigned dst, const void* src) {
    asm volatile("cp.async.cg.shared.global [%0], [%1], 16;" :: "r"(dst), "l"(src));
}
__device__ __forceinline__ void cp_commit() { asm volatile("cp.async.commit_group;"); }
__device__ __forceinline__ void cp_wait0() { asm volatile("cp.async.wait_group 0;" ::: "memory"); }
__device__ __forceinline__ void cp_wait1() { asm volatile("cp.async.wait_group 1;" ::: "memory"); }

__device__ __forceinline__ void ldm4(unsigned* r, unsigned a) {
    asm volatile("ldmatrix.sync.aligned.m8n8.x4.shared.b16 {%0,%1,%2,%3}, [%4];"
                 : "=r"(r[0]), "=r"(r[1]), "=r"(r[2]), "=r"(r[3]) : "r"(a));
}
__device__ __forceinline__ void ldm4t(unsigned* r, unsigned a) {
    asm volatile("ldmatrix.sync.aligned.m8n8.x4.trans.shared.b16 {%0,%1,%2,%3}, [%4];"
                 : "=r"(r[0]), "=r"(r[1]), "=r"(r[2]), "=r"(r[3]) : "r"(a));
}
__device__ __forceinline__ void mma_f16(float* c, const unsigned* a, unsigned b0, unsigned b1) {
    asm volatile(
        "mma.sync.aligned.m16n8k16.row.col.f32.f16.f16.f32 "
        "{%0,%1,%2,%3},{%4,%5,%6,%7},{%8,%9},{%0,%1,%2,%3};"
        : "+f"(c[0]), "+f"(c[1]), "+f"(c[2]), "+f"(c[3])
        : "r"(a[0]), "r"(a[1]), "r"(a[2]), "r"(a[3]), "r"(b0), "r"(b1));
}
__device__ __forceinline__ void split2(float a, float b, h2& h, h2& l) {
    h = __floats2half2_rn(a, b);
    float2 hf = __half22float2(h);
    l = __floats2half2_rn(a - hf.x, b - hf.y);
}
__device__ __forceinline__ h2 hi2(float a, float b) {
    return __floats2half2_rn(a, b);
}
__device__ __forceinline__ float gelu_exact(float x) {
    return 0.5f * x * (1.0f + erff(x * 0.70710678118654752f));
}
__device__ __forceinline__ float brsum(float v, float* sb) {
    int t = threadIdx.x;
    sb[t] = v; __syncthreads();
    for (int s = 128; s > 0; s >>= 1) { if (t < s) sb[t] += sb[t + s]; __syncthreads(); }
    float r = sb[0]; __syncthreads(); return r;
}
__device__ __forceinline__ float brmax(float v, float* sb) {
    int t = threadIdx.x;
    sb[t] = v; __syncthreads();
    for (int s = 128; s > 0; s >>= 1) { if (t < s) sb[t] = fmaxf(sb[t], sb[t + s]); __syncthreads(); }
    float r = sb[0]; __syncthreads(); return r;
}

#define CBUF 29184             // Ah(10240) + Al(10240) + Bh(8704)
#define CSMEM3 87552           // 3 buffers
#define NBUF 30720             // Qh + Ql + Kh
#define NSMEM 61440

// conv1x1 GEMM (fp16 2-pass): C[b](M x GN) = A[b](M x K) @ Bh[b](K x GN)
// epi bits: 1 gelu, 2 +R, 4 split hi+lo out, 8 fp32 out, 32 split hi-only out
__global__ __launch_bounds__(256, 2)
void gemm_cp(const __half* __restrict__ Ah, const __half* __restrict__ Al, size_t aBs,
             const __half* __restrict__ Bh, size_t bBs,
             float* __restrict__ C, __half* __restrict__ Ch, __half* __restrict__ Cl,
             size_t cBs, size_t oGrp, const float* __restrict__ R,
             int K, int epi) {
    extern __shared__ char smem[];
    int tid = threadIdx.x, wid = tid >> 5, lane = tid & 31;
    int wm = wid & 1, wn = wid >> 1;
    int oBase = blockIdx.y * 128, nBase = blockIdx.x * 128;
    int b = blockIdx.z;
    Ah += (size_t)b * aBs; Al += (size_t)b * aBs;
    Bh += (size_t)b * bBs;

    unsigned sb0 = s2u(smem);
    auto stage = [&](int kk, int buf) {
        unsigned base = sb0 + buf * CBUF;
#pragma unroll
        for (int i = 0; i < 6; i++) {
            int c = tid + 256 * i;
            if (i < 4) {
                int p = c >> 9, r = (c >> 2) & 127, s = c & 3;
                const __half* src = (p ? Al : Ah) + (size_t)(oBase + r) * K + kk + s * 8;
                cpa16(base + p * 10240 + r * 80 + s * 16, src);
            } else {
                int c2 = c - 1024;               // 0..511
                int r = (c2 >> 4) & 31, s = c2 & 15;
                const __half* src = Bh + (size_t)(kk + r) * GN + nBase + s * 8;
                cpa16(base + 20480 + r * 272 + s * 16, src);
            }
        }
        cp_commit();
    };

    float acc[4][4][4];
#pragma unroll
    for (int i = 0; i < 4; i++)
#pragma unroll
        for (int j = 0; j < 4; j++)
#pragma unroll
            for (int q = 0; q < 4; q++) acc[i][j][q] = 0.0f;

    unsigned aRow = (unsigned)(wm * 64 + (lane & 15));
    unsigned aKof = (unsigned)((lane >> 4) * 8);
    unsigned bKrow = (unsigned)((lane & 7) + ((lane >> 3) & 1) * 8);
    unsigned bNcol = (unsigned)(wn * 32 + ((lane >> 4) & 1) * 8);

    int KT = K >> 5;
    stage(0, 0);
    if (KT > 1) stage(32, 1);
    int buf = 0;
    for (int t = 0; t < KT; t++) {
        if (t + 2 < KT) cp_wait1(); else cp_wait0();
        __syncthreads();
        if (t + 2 < KT) {
            int nb = buf + 2; if (nb >= 3) nb -= 3;
            stage((t + 2) * 32, nb);
        }

        const __half* sA0 = (const __half*)(smem + buf * CBUF);
        const __half* sA1 = (const __half*)(smem + buf * CBUF + 10240);
        const __half* sB0 = (const __half*)(smem + buf * CBUF + 20480);
#pragma unroll
        for (int ks = 0; ks < 32; ks += 16) {
            unsigned ah[4][4], bh2r[2][4];
#pragma unroll
            for (int mt = 0; mt < 4; mt++)
                ldm4(ah[mt], s2u(&sA0[(aRow + mt * 16) * 40 + ks + aKof]));
#pragma unroll
            for (int n2 = 0; n2 < 2; n2++)
                ldm4t(bh2r[n2], s2u(&sB0[(bKrow + ks) * 136 + bNcol + n2 * 16]));
#pragma unroll
            for (int mt = 0; mt < 4; mt++)
#pragma unroll
                for (int nt = 0; nt < 4; nt++)
                    mma_f16(acc[mt][nt], ah[mt], bh2r[nt >> 1][(nt & 1) * 2],
                            bh2r[nt >> 1][(nt & 1) * 2 + 1]);
            unsigned al[4][4];
#pragma unroll
            for (int mt = 0; mt < 4; mt++)
                ldm4(al[mt], s2u(&sA1[(aRow + mt * 16) * 40 + ks + aKof]));
#pragma unroll
            for (int mt = 0; mt < 4; mt++)
#pragma unroll
                for (int nt = 0; nt < 4; nt++)
                    mma_f16(acc[mt][nt], al[mt], bh2r[nt >> 1][(nt & 1) * 2],
                            bh2r[nt >> 1][(nt & 1) * 2 + 1]);
        }
        buf++; if (buf >= 3) buf -= 3;
    }

    int g = lane >> 2, tg = lane & 3;
#pragma unroll
    for (int mt = 0; mt < 4; mt++) {
#pragma unroll
        for (int nt = 0; nt < 4; nt++) {
            int r0 = oBase + wm * 64 + mt * 16 + g;
            int col = nBase + wn * 32 + nt * 8 + tg * 2;
            float* c = acc[mt][nt];
#pragma unroll
            for (int h2i = 0; h2i < 2; h2i++) {
                int rr = r0 + h2i * 8;
                size_t base = (size_t)(rr >> 8) * oGrp + (size_t)b * cBs
                            + (size_t)(rr & 255) * GN + col;
                float o0 = c[2 * h2i], o1 = c[2 * h2i + 1];
                if (epi & 2) {
                    float2 rv = *(const float2*)&R[base];
                    o0 += rv.x; o1 += rv.y;
                }
                if (epi & 1) { o0 = gelu_exact(o0); o1 = gelu_exact(o1); }
                if (epi & 8) *(float2*)&C[base] = make_float2(o0, o1);
                if (epi & 4) {
                    h2 h, l;
                    split2(o0, o1, h, l);
                    *(h2*)&Ch[base] = h;
                    *(h2*)&Cl[base] = l;
                }
                if (epi & 32) *(h2*)&Ch[base] = hi2(o0, o1);
            }
        }
    }
}

// NT score GEMM (fp16 2-pass): P[z][i][j] = sum_{n in chunk} Q[i][n] * Kh[j][n]
__global__ __launch_bounds__(256, 2)
void gemmnt_cp(const __half* __restrict__ Qh, const __half* __restrict__ Ql, size_t qBs,
               const __half* __restrict__ Kh, size_t kBs,
               float* __restrict__ P, int J, int nsplit) {
    extern __shared__ char smem[];
    int tid = threadIdx.x, wid = tid >> 5, lane = tid & 31;
    int wm = wid & 1, wn = wid >> 1;
    int z = blockIdx.z, b = z / nsplit, s = z % nsplit;
    Qh += (size_t)b * qBs; Ql += (size_t)b * qBs;
    Kh += (size_t)b * kBs;
    int iBase = blockIdx.y * 128, jBase = blockIdx.x * 128;
    const int chunk = GN / nsplit;
    int n0 = s * chunk;
    unsigned sb0 = s2u(smem);

    auto stage = [&](int kk, int buf) {
        unsigned base = sb0 + buf * NBUF;
#pragma unroll
        for (int i = 0; i < 6; i++) {
            int c = tid + 256 * i;
            int p = c >> 9, r = (c >> 2) & 127, sg = c & 3;
            const __half* pl[3] = { Qh, Ql, Kh };
            int rowBase = (p < 2) ? iBase : jBase;
            const __half* src = pl[p] + (size_t)(rowBase + r) * GN + n0 + kk + sg * 8;
            cpa16(base + p * 10240 + r * 80 + sg * 16, src);
        }
        cp_commit();
    };

    float acc[4][4][4];
#pragma unroll
    for (int i = 0; i < 4; i++)
#pragma unroll
        for (int j = 0; j < 4; j++)
#pragma unroll
            for (int q = 0; q < 4; q++) acc[i][j][q] = 0.0f;

    unsigned aRow = (unsigned)(wm * 64 + (lane & 15));
    unsigned aKof = (unsigned)((lane >> 4) * 8);
    unsigned bJrow = (unsigned)(wn * 32 + (lane & 7) + ((lane >> 4) & 1) * 8);
    unsigned bKof = (unsigned)(((lane >> 3) & 1) * 8);

    int KT = chunk >> 5;
    stage(0, 0);
    for (int t = 0; t < KT; t++) {
        int cb = t & 1;
        if (t + 1 < KT) {
            stage((t + 1) * 32, cb ^ 1);
            cp_wait1();
        } else {
            cp_wait0();
        }
        __syncthreads();

        const __half* sQ0 = (const __half*)(smem + cb * NBUF);
        const __half* sQ1 = (const __half*)(smem + cb * NBUF + 10240);
        const __half* sK0 = (const __half*)(smem + cb * NBUF + 20480);
#pragma unroll
        for (int ks = 0; ks < 32; ks += 16) {
            unsigned ah[4][4], bh2r[2][4];
#pragma unroll
            for (int mt = 0; mt < 4; mt++)
                ldm4(ah[mt], s2u(&sQ0[(aRow + mt * 16) * 40 + ks + aKof]));
#pragma unroll
            for (int n2 = 0; n2 < 2; n2++)
                ldm4(bh2r[n2], s2u(&sK0[(bJrow + n2 * 16) * 40 + ks + bKof]));
#pragma unroll
            for (int mt = 0; mt < 4; mt++)
#pragma unroll
                for (int nt = 0; nt < 4; nt++)
                    mma_f16(acc[mt][nt], ah[mt], bh2r[nt >> 1][(nt & 1) * 2],
                            bh2r[nt >> 1][(nt & 1) * 2 + 1]);
            unsigned al[4][4];
#pragma unroll
            for (int mt = 0; mt < 4; mt++)
                ldm4(al[mt], s2u(&sQ1[(aRow + mt * 16) * 40 + ks + aKof]));
#pragma unroll
            for (int mt = 0; mt < 4; mt++)
#pragma unroll
                for (int nt = 0; nt < 4; nt++)
                    mma_f16(acc[mt][nt], al[mt], bh2r[nt >> 1][(nt & 1) * 2],
                            bh2r[nt >> 1][(nt & 1) * 2 + 1]);
        }
        __syncthreads();
    }

    int g = lane >> 2, tg = lane & 3;
#pragma unroll
    for (int mt = 0; mt < 4; mt++) {
#pragma unroll
        for (int nt = 0; nt < 4; nt++) {
            int r0 = iBase + wm * 64 + mt * 16 + g;
            int col = jBase + wn * 32 + nt * 8 + tg * 2;
            float* c = acc[mt][nt];
#pragma unroll
            for (int h2i = 0; h2i < 2; h2i++) {
                size_t base = ((size_t)z * 256 + r0 + h2i * 8) * J + col;
                *(float2*)&P[base] = make_float2(c[2 * h2i], c[2 * h2i + 1]);
            }
        }
    }
}

// weights: hi + lo split (A operands)
__global__ __launch_bounds__(256)
void split_w8(const float* w0, const float* w1, const float* w2, const float* w3,
              const float* w4, const float* w5, const float* w6, const float* w7,
              __half* __restrict__ H, __half* __restrict__ L) {
    const float* srcs[8] = { w0, w1, w2, w3, w4, w5, w6, w7 };
    int w = blockIdx.y;
    const float* X = srcs[w];
    int i = blockIdx.x * 256 + threadIdx.x;
    float4 v = ((const float4*)X)[i];
    h2 h0, l0, h1, l1;
    split2(v.x, v.y, h0, l0);
    split2(v.z, v.w, h1, l1);
    size_t o = (size_t)w * 32768 + 2 * i;
    ((h2*)H)[o] = h0; ((h2*)H)[o + 1] = h1;
    ((h2*)L)[o] = l0; ((h2*)L)[o + 1] = l1;
}

// hi-only convert (B-only tensors: feat, kv)
__global__ __launch_bounds__(256)
void split_hi(const float* __restrict__ X, __half* __restrict__ H, int n4) {
    int i = blockIdx.x * 256 + threadIdx.x;
    if (i < n4) {
        float4 v = ((const float4*)X)[i];
        ((h2*)H)[2 * i] = hi2(v.x, v.y);
        ((h2*)H)[2 * i + 1] = hi2(v.z, v.w);
    }
}

// instance norm -> hi plane only (norm output is B-only)
__global__ __launch_bounds__(256)
void inorm_hi(const float* __restrict__ X, __half* __restrict__ H,
              const float* __restrict__ gamma, const float* __restrict__ beta) {
    __shared__ float sb[256];
    int row = blockIdx.x, cch = row & (ECH - 1);
    const float4* xr = (const float4*)(X + (size_t)row * GN);
    h2* hr = (h2*)(H + (size_t)row * GN);
    float s = 0.f, ss = 0.f;
    for (int i = threadIdx.x; i < GN / 4; i += 256) {
        float4 v = xr[i];
        s += v.x + v.y + v.z + v.w;
        ss += v.x * v.x + v.y * v.y + v.z * v.z + v.w * v.w;
    }
    float tot = brsum(s, sb), tot2 = brsum(ss, sb);
    const float inv = 1.0f / (float)GN;
    float mu = tot * inv, var = tot2 * inv - mu * mu;
    float rstd = rsqrtf(var + 1e-5f);
    float a = rstd * gamma[cch], bb = beta[cch] - mu * a;
    for (int i = threadIdx.x; i < GN / 4; i += 256) {
        float4 v = xr[i];
        hr[2 * i] = hi2(v.x * a + bb, v.y * a + bb);
        hr[2 * i + 1] = hi2(v.z * a + bb, v.w * a + bb);
    }
}

__global__ __launch_bounds__(256)
void softmax_split(const float* __restrict__ P, __half* __restrict__ SH,
                   __half* __restrict__ SL, int J, float scale, int nsplit) {
    __shared__ float rowbuf[512];
    __shared__ float sb[256];
    int row = blockIdx.x, b = row >> 8, i = row & 255, tid = threadIdx.x;
    for (int j = tid; j < J; j += 256) {
        float v = 0.f;
        for (int s = 0; s < nsplit; s++)
            v += P[(((size_t)(b * nsplit + s) * 256) + i) * J + j];
        rowbuf[j] = v * scale;
    }
    __syncthreads();
    float ls = 0.f;
    for (int j = tid; j < J; j += 256) ls += rowbuf[j];
    float mean = brsum(ls, sb) / (float)J;
    float lv = 0.f;
    for (int j = tid; j < J; j += 256) { float d = rowbuf[j] - mean; lv += d * d; }
    float rstd = rsqrtf(brsum(lv, sb) / (float)J + 1e-5f);
    float lm = -1e30f;
    for (int j = tid; j < J; j += 256) {
        float tt = (rowbuf[j] - mean) * rstd;
        rowbuf[j] = tt;
        lm = fmaxf(lm, tt);
    }
    float mx = brmax(lm, sb);
    float le = 0.f;
    for (int j = tid; j < J; j += 256) {
        float e = expf(rowbuf[j] - mx);
        rowbuf[j] = e;
        le += e;
    }
    float rden = 1.0f / brsum(le, sb);
    size_t ob = ((size_t)b * 256 + i) * J;
    for (int j = tid; j < J; j += 256) {
        float y = rowbuf[j] * rden;
        __half h = __float2half_rn(y);
        SH[ob + j] = h;
        SL[ob + j] = __float2half_rn(y - __half2float(h));
    }
}

extern "C" void kernel_launch(void* const* d_in, const int* in_sizes, int n_in,
                              void* d_out, int out_size) {
    const float* feat = (const float*)d_in[0];
    const float* kv   = (const float*)d_in[1];
    const float* ag = (const float*)d_in[10];
    const float* ab = (const float*)d_in[11];
    const float* eg = (const float*)d_in[12];
    const float* eb = (const float*)d_in[13];
    float* out = (float*)d_out;

    float *emb, *pre, *pu, *plw;
    __half *fh, *nh, *qkvh, *qkvl, *th, *kvh, *suh, *sul, *slh, *sll, *wh, *wl;
    cudaGetSymbolAddress((void**)&emb, g_emb);
    cudaGetSymbolAddress((void**)&pre, g_pre);
    cudaGetSymbolAddress((void**)&pu, g_pu);
    cudaGetSymbolAddress((void**)&plw, g_plw);
    cudaGetSymbolAddress((void**)&fh, g_fh);
    cudaGetSymbolAddress((void**)&nh, g_nh);
    cudaGetSymbolAddress((void**)&qkvh, g_qkvh); cudaGetSymbolAddress((void**)&qkvl, g_qkvl);
    cudaGetSymbolAddress((void**)&th, g_th);
    cudaGetSymbolAddress((void**)&kvh, g_kvh);
    cudaGetSymbolAddress((void**)&suh, g_suh); cudaGetSymbolAddress((void**)&sul, g_sul);
    cudaGetSymbolAddress((void**)&slh, g_slh); cudaGetSymbolAddress((void**)&sll, g_sll);
    cudaGetSymbolAddress((void**)&wh, g_wh);   cudaGetSymbolAddress((void**)&wl, g_wl);

    __half *qh = qkvh, *ql = qkvl;
    __half *kh = qkvh + TOT4;
    __half *vh = qkvh + 2 * TOT4;

    cudaFuncSetAttribute(gemm_cp, cudaFuncAttributeMaxDynamicSharedMemorySize, CSMEM3);
    cudaFuncSetAttribute(gemmnt_cp, cudaFuncAttributeMaxDynamicSharedMemorySize, NSMEM);

    const float scale = 1.0f / 128.0f;
    dim3 blk(256);
    dim3 g8(GN / 128, 2, 8);
    dim3 g4(GN / 128, 2, 4);

    // #1 weights
    split_w8<<<dim3(64, 8), blk>>>((const float*)d_in[2], (const float*)d_in[3],
                                   (const float*)d_in[4], (const float*)d_in[5],
                                   (const float*)d_in[6], (const float*)d_in[7],
                                   (const float*)d_in[8], (const float*)d_in[9], wh, wl);
    // #2 feat, #3 kv (hi only)
    split_hi<<<32768, blk>>>(feat, fh, 8388608);
    split_hi<<<8192, blk>>>(kv, kvh, 2097152);
    // #4 emb = gelu(w_in @ feat)
    gemm_cp<<<g8, blk, CSMEM3>>>(wh, wl, 0, fh, BSTR, emb, nullptr, nullptr,
                                 BSTR, 0, nullptr, 256, 1 | 8);
    // #5 nrm hi plane
    inorm_hi<<<NB * ECH, blk>>>(emb, nh, ag, ab);
    // #6 fused QKV (M=768, full split out; only q-lo used later) -> PROFILED
    gemm_cp<<<dim3(GN / 128, 6, 4), blk, CSMEM3>>>(wh + 2 * 65536, wl + 2 * 65536, 0,
                                                   nh + TOT4, BSTR,
                                                   nullptr, qkvh, qkvl, BSTR, TOT4,
                                                   nullptr, 256, 4);
    // #7 upper scores (nsplit=16 -> 256 CTAs)
    gemmnt_cp<<<dim3(2, 2, HB * 16), blk, NSMEM>>>(qh, ql, BSTR, kh, BSTR, pu, 256, 16);
    // #8 softmax upper
    softmax_split<<<HB * 256, blk>>>(pu, suh, sul, 256, scale, 16);
    // #9 t = su @ v (hi-only out)
    gemm_cp<<<g4, blk, CSMEM3>>>(suh, sul, 65536, vh, BSTR, nullptr, th, nullptr,
                                 BSTR, 0, nullptr, 256, 32);
    // #10 pre_u = wo_sa @ t + emb_u
    gemm_cp<<<g4, blk, CSMEM3>>>(wh + 5 * 65536, wl + 5 * 65536, 0, th, BSTR,
                                 pre + TOT4, nullptr, nullptr, BSTR, 0,
                                 emb + TOT4, 256, 2 | 8);
    // #11 lower Ql (full split; used as A in #12)
    gemm_cp<<<g4, blk, CSMEM3>>>(wh + 6 * 65536, wl + 6 * 65536, 0, nh, BSTR,
                                 nullptr, qh, ql, BSTR, 0, nullptr, 256, 4);
    // #12 lower scores (nsplit=8, kv shared)
    gemmnt_cp<<<dim3(4, 2, HB * 8), blk, NSMEM>>>(qh, ql, BSTR, kvh, 0, plw, 512, 8);
    // #13 softmax lower
    softmax_split<<<HB * 256, blk>>>(plw, slh, sll, 512, scale, 8);
    // #14 ca = sl @ kv (K=512, hi-only out)
    gemm_cp<<<g4, blk, CSMEM3>>>(slh, sll, 131072, kvh, 0, nullptr, th, nullptr,
                                 BSTR, 0, nullptr, 512, 32);
    // #15 pre_l = wo_ca @ ca + emb_l
    gemm_cp<<<g4, blk, CSMEM3>>>(wh + 7 * 65536, wl + 7 * 65536, 0, th, BSTR,
                                 pre, nullptr, nullptr, BSTR, 0, emb, 256, 2 | 8);
    // #16 nrm2 hi plane
    inorm_hi<<<NB * ECH, blk>>>(pre, nh, eg, eb);
    // #17 out = gelu(w_out @ nrm2)
    gemm_cp<<<g8, blk, CSMEM3>>>(wh + 65536, wl + 65536, 0, nh, BSTR, out,
                                 nullptr, nullptr, BSTR, 0, nullptr, 256, 1 | 8);
}

// round 14
// speedup vs baseline: 1.9130x; 1.4235x over previous
#include <cuda_runtime.h>
#include <cuda_fp16.h>
#include <math.h>

#define GN 16384
#define ECH 256
#define NB 8
#define HB 4
static const size_t BSTR = (size_t)ECH * GN;
static const size_t TOT4 = (size_t)HB * BSTR;
typedef __half2 h2;

__device__ float g_emb[33554432];
__device__ float g_pre[33554432];
__device__ float g_pu[HB * 16 * 256 * 256];     // upper partials (nsplit=16)
__device__ float g_plw[HB * 8 * 256 * 512];     // lower partials (nsplit=8)
__device__ __half g_fh[33554432];
__device__ __half g_nh[33554432];
__device__ __half g_qkvh[50331648];
__device__ __half g_th[16777216];
__device__ __half g_kvh[8388608];
__device__ __half g_suh[1048576];
__device__ __half g_slh[1048576];
__device__ __half g_wh[524288];                 // 8 x 65536 weight slots (hi only)

__device__ __forceinline__ unsigned s2u(const void* p) {
    return (unsigned)__cvta_generic_to_shared(p);
}
__device__ __forceinline__ void cpa16(unsigned dst, const void* src) {
    asm volatile("cp.async.cg.shared.global [%0], [%1], 16;" :: "r"(dst), "l"(src));
}
__device__ __forceinline__ void cp_commit() { asm volatile("cp.async.commit_group;"); }
__device__ __forceinline__ void cp_wait0() { asm volatile("cp.async.wait_group 0;" ::: "memory"); }
__device__ __forceinline__ void cp_wait1() { asm volatile("cp.async.wait_group 1;" ::: "memory"); }

__device__ __forceinline__ void ldm4(unsigned* r, unsigned a) {
    asm volatile("ldmatrix.sync.aligned.m8n8.x4.shared.b16 {%0,%1,%2,%3}, [%4];"
                 : "=r"(r[0]), "=r"(r[1]), "=r"(r[2]), "=r"(r[3]) : "r"(a));
}
__device__ __forceinline__ void ldm4t(unsigned* r, unsigned a) {
    asm volatile("ldmatrix.sync.aligned.m8n8.x4.trans.shared.b16 {%0,%1,%2,%3}, [%4];"
                 : "=r"(r[0]), "=r"(r[1]), "=r"(r[2]), "=r"(r[3]) : "r"(a));
}
__device__ __forceinline__ void mma_f16(float* c, const unsigned* a, unsigned b0, unsigned b1) {
    asm volatile(
        "mma.sync.aligned.m16n8k16.row.col.f32.f16.f16.f32 "
        "{%0,%1,%2,%3},{%4,%5,%6,%7},{%8,%9},{%0,%1,%2,%3};"
        : "+f"(c[0]), "+f"(c[1]), "+f"(c[2]), "+f"(c[3])
        : "r"(a[0]), "r"(a[1]), "r"(a[2]), "r"(a[3]), "r"(b0), "r"(b1));
}
__device__ __forceinline__ h2 hi2(float a, float b) {
    return __floats2half2_rn(a, b);
}
__device__ __forceinline__ float gelu_exact(float x) {
    return 0.5f * x * (1.0f + erff(x * 0.70710678118654752f));
}
__device__ __forceinline__ float brsum(float v, float* sb) {
    int t = threadIdx.x;
    sb[t] = v; __syncthreads();
    for (int s = 128; s > 0; s >>= 1) { if (t < s) sb[t] += sb[t + s]; __syncthreads(); }
    float r = sb[0]; __syncthreads(); return r;
}
__device__ __forceinline__ float brmax(float v, float* sb) {
    int t = threadIdx.x;
    sb[t] = v; __syncthreads();
    for (int s = 128; s > 0; s >>= 1) { if (t < s) sb[t] = fmaxf(sb[t], sb[t + s]); __syncthreads(); }
    float r = sb[0]; __syncthreads(); return r;
}

#define CBUF 18944             // Ah(10240) + Bh(8704)
#define CSMEM3 56832           // 3 buffers
#define NBUF 20480             // Qh + Kh
#define NSMEM 40960

// conv1x1 GEMM (fp16 1-pass): C[b](M x GN) = Ah[b](M x K) @ Bh[b](K x GN)
// epi bits: 1 gelu, 2 +R, 8 fp32 out, 32 half out. Row-group stride oGrp.
__global__ __launch_bounds__(256, 2)
void gemm_cp(const __half* __restrict__ Ah, size_t aBs,
             const __half* __restrict__ Bh, size_t bBs,
             float* __restrict__ C, __half* __restrict__ Ch,
             size_t cBs, size_t oGrp, const float* __restrict__ R,
             int K, int epi) {
    extern __shared__ char smem[];
    int tid = threadIdx.x, wid = tid >> 5, lane = tid & 31;
    int wm = wid & 1, wn = wid >> 1;
    int oBase = blockIdx.y * 128, nBase = blockIdx.x * 128;
    int b = blockIdx.z;
    Ah += (size_t)b * aBs;
    Bh += (size_t)b * bBs;

    unsigned sb0 = s2u(smem);
    auto stage = [&](int kk, int buf) {
        unsigned base = sb0 + buf * CBUF;
#pragma unroll
        for (int i = 0; i < 4; i++) {
            int c = tid + 256 * i;
            if (i < 2) {                         // A hi: 128 rows x 32 halfs
                int r = c >> 2, s = c & 3;
                const __half* src = Ah + (size_t)(oBase + r) * K + kk + s * 8;
                cpa16(base + r * 80 + s * 16, src);
            } else {                             // B hi: 32 k-rows x 128 halfs
                int c2 = c - 512;
                int r = c2 >> 4, s = c2 & 15;
                const __half* src = Bh + (size_t)(kk + r) * GN + nBase + s * 8;
                cpa16(base + 10240 + r * 272 + s * 16, src);
            }
        }
        cp_commit();
    };

    float acc[4][4][4];
#pragma unroll
    for (int i = 0; i < 4; i++)
#pragma unroll
        for (int j = 0; j < 4; j++)
#pragma unroll
            for (int q = 0; q < 4; q++) acc[i][j][q] = 0.0f;

    unsigned aRow = (unsigned)(wm * 64 + (lane & 15));
    unsigned aKof = (unsigned)((lane >> 4) * 8);
    unsigned bKrow = (unsigned)((lane & 7) + ((lane >> 3) & 1) * 8);
    unsigned bNcol = (unsigned)(wn * 32 + ((lane >> 4) & 1) * 8);

    int KT = K >> 5;
    stage(0, 0);
    if (KT > 1) stage(32, 1);
    int buf = 0;
    for (int t = 0; t < KT; t++) {
        if (t + 2 < KT) cp_wait1(); else cp_wait0();
        __syncthreads();
        if (t + 2 < KT) {
            int nb = buf + 2; if (nb >= 3) nb -= 3;
            stage((t + 2) * 32, nb);
        }

        const __half* sA0 = (const __half*)(smem + buf * CBUF);
        const __half* sB0 = (const __half*)(smem + buf * CBUF + 10240);
#pragma unroll
        for (int ks = 0; ks < 32; ks += 16) {
            unsigned ah[4][4], bh2r[2][4];
#pragma unroll
            for (int mt = 0; mt < 4; mt++)
                ldm4(ah[mt], s2u(&sA0[(aRow + mt * 16) * 40 + ks + aKof]));
#pragma unroll
            for (int n2 = 0; n2 < 2; n2++)
                ldm4t(bh2r[n2], s2u(&sB0[(bKrow + ks) * 136 + bNcol + n2 * 16]));
#pragma unroll
            for (int mt = 0; mt < 4; mt++)
#pragma unroll
                for (int nt = 0; nt < 4; nt++)
                    mma_f16(acc[mt][nt], ah[mt], bh2r[nt >> 1][(nt & 1) * 2],
                            bh2r[nt >> 1][(nt & 1) * 2 + 1]);
        }
        buf++; if (buf >= 3) buf -= 3;
    }

    int g = lane >> 2, tg = lane & 3;
#pragma unroll
    for (int mt = 0; mt < 4; mt++) {
#pragma unroll
        for (int nt = 0; nt < 4; nt++) {
            int r0 = oBase + wm * 64 + mt * 16 + g;
            int col = nBase + wn * 32 + nt * 8 + tg * 2;
            float* c = acc[mt][nt];
#pragma unroll
            for (int h2i = 0; h2i < 2; h2i++) {
                int rr = r0 + h2i * 8;
                size_t base = (size_t)(rr >> 8) * oGrp + (size_t)b * cBs
                            + (size_t)(rr & 255) * GN + col;
                float o0 = c[2 * h2i], o1 = c[2 * h2i + 1];
                if (epi & 2) {
                    float2 rv = *(const float2*)&R[base];
                    o0 += rv.x; o1 += rv.y;
                }
                if (epi & 1) { o0 = gelu_exact(o0); o1 = gelu_exact(o1); }
                if (epi & 8) *(float2*)&C[base] = make_float2(o0, o1);
                if (epi & 32) *(h2*)&Ch[base] = hi2(o0, o1);
            }
        }
    }
}

// NT score GEMM (fp16 1-pass): P[z][i][j] = sum_{n in chunk} Qh[i][n] * Kh[j][n]
__global__ __launch_bounds__(256, 2)
void gemmnt_cp(const __half* __restrict__ Qh, size_t qBs,
               const __half* __restrict__ Kh, size_t kBs,
               float* __restrict__ P, int J, int nsplit) {
    extern __shared__ char smem[];
    int tid = threadIdx.x, wid = tid >> 5, lane = tid & 31;
    int wm = wid & 1, wn = wid >> 1;
    int z = blockIdx.z, b = z / nsplit, s = z % nsplit;
    Qh += (size_t)b * qBs;
    Kh += (size_t)b * kBs;
    int iBase = blockIdx.y * 128, jBase = blockIdx.x * 128;
    const int chunk = GN / nsplit;
    int n0 = s * chunk;
    unsigned sb0 = s2u(smem);

    auto stage = [&](int kk, int buf) {
        unsigned base = sb0 + buf * NBUF;
#pragma unroll
        for (int i = 0; i < 4; i++) {
            int c = tid + 256 * i;
            int p = c >> 9, c2 = c & 511;
            int r = c2 >> 2, sg = c2 & 3;
            const __half* src = (p ? Kh + (size_t)(jBase + r) * GN
                                   : Qh + (size_t)(iBase + r) * GN) + n0 + kk + sg * 8;
            cpa16(base + p * 10240 + r * 80 + sg * 16, src);
        }
        cp_commit();
    };

    float acc[4][4][4];
#pragma unroll
    for (int i = 0; i < 4; i++)
#pragma unroll
        for (int j = 0; j < 4; j++)
#pragma unroll
            for (int q = 0; q < 4; q++) acc[i][j][q] = 0.0f;

    unsigned aRow = (unsigned)(wm * 64 + (lane & 15));
    unsigned aKof = (unsigned)((lane >> 4) * 8);
    unsigned bJrow = (unsigned)(wn * 32 + (lane & 7) + ((lane >> 4) & 1) * 8);
    unsigned bKof = (unsigned)(((lane >> 3) & 1) * 8);

    int KT = chunk >> 5;
    stage(0, 0);
    for (int t = 0; t < KT; t++) {
        int cb = t & 1;
        if (t + 1 < KT) {
            stage((t + 1) * 32, cb ^ 1);
            cp_wait1();
        } else {
            cp_wait0();
        }
        __syncthreads();

        const __half* sQ0 = (const __half*)(smem + cb * NBUF);
        const __half* sK0 = (const __half*)(smem + cb * NBUF + 10240);
#pragma unroll
        for (int ks = 0; ks < 32; ks += 16) {
            unsigned ah[4][4], bh2r[2][4];
#pragma unroll
            for (int mt = 0; mt < 4; mt++)
                ldm4(ah[mt], s2u(&sQ0[(aRow + mt * 16) * 40 + ks + aKof]));
#pragma unroll
            for (int n2 = 0; n2 < 2; n2++)
                ldm4(bh2r[n2], s2u(&sK0[(bJrow + n2 * 16) * 40 + ks + bKof]));
#pragma unroll
            for (int mt = 0; mt < 4; mt++)
#pragma unroll
                for (int nt = 0; nt < 4; nt++)
                    mma_f16(acc[mt][nt], ah[mt], bh2r[nt >> 1][(nt & 1) * 2],
                            bh2r[nt >> 1][(nt & 1) * 2 + 1]);
        }
        __syncthreads();
    }

    int g = lane >> 2, tg = lane & 3;
#pragma unroll
    for (int mt = 0; mt < 4; mt++) {
#pragma unroll
        for (int nt = 0; nt < 4; nt++) {
            int r0 = iBase + wm * 64 + mt * 16 + g;
            int col = jBase + wn * 32 + nt * 8 + tg * 2;
            float* c = acc[mt][nt];
#pragma unroll
            for (int h2i = 0; h2i < 2; h2i++) {
                size_t base = ((size_t)z * 256 + r0 + h2i * 8) * J + col;
                *(float2*)&P[base] = make_float2(c[2 * h2i], c[2 * h2i + 1]);
            }
        }
    }
}

// weights: hi-only convert, 8 slots in one launch
__global__ __launch_bounds__(256)
void split_w8(const float* w0, const float* w1, const float* w2, const float* w3,
              const float* w4, const float* w5, const float* w6, const float* w7,
              __half* __restrict__ H) {
    const float* srcs[8] = { w0, w1, w2, w3, w4, w5, w6, w7 };
    int w = blockIdx.y;
    const float* X = srcs[w];
    int i = blockIdx.x * 256 + threadIdx.x;
    float4 v = ((const float4*)X)[i];
    size_t o = (size_t)w * 32768 + 2 * i;
    ((h2*)H)[o] = hi2(v.x, v.y);
    ((h2*)H)[o + 1] = hi2(v.z, v.w);
}

__global__ __launch_bounds__(256)
void split_hi(const float* __restrict__ X, __half* __restrict__ H, int n4) {
    int i = blockIdx.x * 256 + threadIdx.x;
    if (i < n4) {
        float4 v = ((const float4*)X)[i];
        ((h2*)H)[2 * i] = hi2(v.x, v.y);
        ((h2*)H)[2 * i + 1] = hi2(v.z, v.w);
    }
}

__global__ __launch_bounds__(256)
void inorm_hi(const float* __restrict__ X, __half* __restrict__ H,
              const float* __restrict__ gamma, const float* __restrict__ beta) {
    __shared__ float sb[256];
    int row = blockIdx.x, cch = row & (ECH - 1);
    const float4* xr = (const float4*)(X + (size_t)row * GN);
    h2* hr = (h2*)(H + (size_t)row * GN);
    float s = 0.f, ss = 0.f;
    for (int i = threadIdx.x; i < GN / 4; i += 256) {
        float4 v = xr[i];
        s += v.x + v.y + v.z + v.w;
        ss += v.x * v.x + v.y * v.y + v.z * v.z + v.w * v.w;
    }
    float tot = brsum(s, sb), tot2 = brsum(ss, sb);
    const float inv = 1.0f / (float)GN;
    float mu = tot * inv, var = tot2 * inv - mu * mu;
    float rstd = rsqrtf(var + 1e-5f);
    float a = rstd * gamma[cch], bb = beta[cch] - mu * a;
    for (int i = threadIdx.x; i < GN / 4; i += 256) {
        float4 v = xr[i];
        hr[2 * i] = hi2(v.x * a + bb, v.y * a + bb);
        hr[2 * i + 1] = hi2(v.z * a + bb, v.w * a + bb);
    }
}

__global__ __launch_bounds__(256)
void softmax_hi(const float* __restrict__ P, __half* __restrict__ SH,
                int J, float scale, int nsplit) {
    __shared__ float rowbuf[512];
    __shared__ float sb[256];
    int row = blockIdx.x, b = row >> 8, i = row & 255, tid = threadIdx.x;
    for (int j = tid; j < J; j += 256) {
        float v = 0.f;
        for (int s = 0; s < nsplit; s++)
            v += P[(((size_t)(b * nsplit + s) * 256) + i) * J + j];
        rowbuf[j] = v * scale;
    }
    __syncthreads();
    float ls = 0.f;
    for (int j = tid; j < J; j += 256) ls += rowbuf[j];
    float mean = brsum(ls, sb) / (float)J;
    float lv = 0.f;
    for (int j = tid; j < J; j += 256) { float d = rowbuf[j] - mean; lv += d * d; }
    float rstd = rsqrtf(brsum(lv, sb) / (float)J + 1e-5f);
    float lm = -1e30f;
    for (int j = tid; j < J; j += 256) {
        float tt = (rowbuf[j] - mean) * rstd;
        rowbuf[j] = tt;
        lm = fmaxf(lm, tt);
    }
    float mx = brmax(lm, sb);
    float le = 0.f;
    for (int j = tid; j < J; j += 256) {
        float e = expf(rowbuf[j] - mx);
        rowbuf[j] = e;
        le += e;
    }
    float rden = 1.0f / brsum(le, sb);
    size_t ob = ((size_t)b * 256 + i) * J;
    for (int j = tid; j < J; j += 256)
        SH[ob + j] = __float2half_rn(rowbuf[j] * rden);
}

extern "C" void kernel_launch(void* const* d_in, const int* in_sizes, int n_in,
                              void* d_out, int out_size) {
    const float* feat = (const float*)d_in[0];
    const float* kv   = (const float*)d_in[1];
    const float* ag = (const float*)d_in[10];
    const float* ab = (const float*)d_in[11];
    const float* eg = (const float*)d_in[12];
    const float* eb = (const float*)d_in[13];
    float* out = (float*)d_out;

    float *emb, *pre, *pu, *plw;
    __half *fh, *nh, *qkvh, *th, *kvh, *suh, *slh, *wh;
    cudaGetSymbolAddress((void**)&emb, g_emb);
    cudaGetSymbolAddress((void**)&pre, g_pre);
    cudaGetSymbolAddress((void**)&pu, g_pu);
    cudaGetSymbolAddress((void**)&plw, g_plw);
    cudaGetSymbolAddress((void**)&fh, g_fh);
    cudaGetSymbolAddress((void**)&nh, g_nh);
    cudaGetSymbolAddress((void**)&qkvh, g_qkvh);
    cudaGetSymbolAddress((void**)&th, g_th);
    cudaGetSymbolAddress((void**)&kvh, g_kvh);
    cudaGetSymbolAddress((void**)&suh, g_suh);
    cudaGetSymbolAddress((void**)&slh, g_slh);
    cudaGetSymbolAddress((void**)&wh, g_wh);

    __half *qh = qkvh;
    __half *kh = qkvh + TOT4;
    __half *vh = qkvh + 2 * TOT4;

    cudaFuncSetAttribute(gemm_cp, cudaFuncAttributeMaxDynamicSharedMemorySize, CSMEM3);
    cudaFuncSetAttribute(gemmnt_cp, cudaFuncAttributeMaxDynamicSharedMemorySize, NSMEM);

    const float scale = 1.0f / 128.0f;
    dim3 blk(256);
    dim3 g8(GN / 128, 2, 8);
    dim3 g4(GN / 128, 2, 4);

    // #1 weights (hi only)
    split_w8<<<dim3(64, 8), blk>>>((const float*)d_in[2], (const float*)d_in[3],
                                   (const float*)d_in[4], (const float*)d_in[5],
                                   (const float*)d_in[6], (const float*)d_in[7],
                                   (const float*)d_in[8], (const float*)d_in[9], wh);
    // #2 feat, #3 kv
    split_hi<<<32768, blk>>>(feat, fh, 8388608);
    split_hi<<<8192, blk>>>(kv, kvh, 2097152);
    // #4 emb = gelu(w_in @ feat)
    gemm_cp<<<g8, blk, CSMEM3>>>(wh, 0, fh, BSTR, emb, nullptr,
                                 BSTR, 0, nullptr, 256, 1 | 8);
    // #5 nrm hi plane
    inorm_hi<<<NB * ECH, blk>>>(emb, nh, ag, ab);
    // #6 fused QKV (M=768) -> PROFILED
    gemm_cp<<<dim3(GN / 128, 6, 4), blk, CSMEM3>>>(wh + 2 * 65536, 0,
                                                   nh + TOT4, BSTR,
                                                   nullptr, qkvh, BSTR, TOT4,
                                                   nullptr, 256, 32);
    // #7 upper scores (nsplit=16 -> 256 CTAs)
    gemmnt_cp<<<dim3(2, 2, HB * 16), blk, NSMEM>>>(qh, BSTR, kh, BSTR, pu, 256, 16);
    // #8 softmax upper
    softmax_hi<<<HB * 256, blk>>>(pu, suh, 256, scale, 16);
    // #9 t = su @ v
    gemm_cp<<<g4, blk, CSMEM3>>>(suh, 65536, vh, BSTR, nullptr, th,
                                 BSTR, 0, nullptr, 256, 32);
    // #10 pre_u = wo_sa @ t + emb_u
    gemm_cp<<<g4, blk, CSMEM3>>>(wh + 5 * 65536, 0, th, BSTR,
                                 pre + TOT4, nullptr, BSTR, 0,
                                 emb + TOT4, 256, 2 | 8);
    // #11 lower Ql
    gemm_cp<<<g4, blk, CSMEM3>>>(wh + 6 * 65536, 0, nh, BSTR,
                                 nullptr, qh, BSTR, 0, nullptr, 256, 32);
    // #12 lower scores (nsplit=8, kv shared)
    gemmnt_cp<<<dim3(4, 2, HB * 8), blk, NSMEM>>>(qh, BSTR, kvh, 0, plw, 512, 8);
    // #13 softmax lower
    softmax_hi<<<HB * 256, blk>>>(plw, slh, 512, scale, 8);
    // #14 ca = sl @ kv (K=512)
    gemm_cp<<<g4, blk, CSMEM3>>>(slh, 131072, kvh, 0, nullptr, th,
                                 BSTR, 0, nullptr, 512, 32);
    // #15 pre_l = wo_ca @ ca + emb_l
    gemm_cp<<<g4, blk, CSMEM3>>>(wh + 7 * 65536, 0, th, BSTR,
                                 pre, nullptr, BSTR, 0, emb, 256, 2 | 8);
    // #16 nrm2
    inorm_hi<<<NB * ECH, blk>>>(pre, nh, eg, eb);
    // #17 out = gelu(w_out @ nrm2)
    gemm_cp<<<g8, blk, CSMEM3>>>(wh + 65536, 0, nh, BSTR, out, nullptr,
                                 BSTR, 0, nullptr, 256, 1 | 8);
}

// round 15
// speedup vs baseline: 1.9560x; 1.0225x over previous
#include <cuda_runtime.h>
#include <cuda_fp16.h>
#include <math.h>

#define GN 16384
#define ECH 256
#define NB 8
#define HB 4
static const size_t BSTR = (size_t)ECH * GN;
static const size_t TOT4 = (size_t)HB * BSTR;
typedef __half2 h2;

__device__ float g_emb[33554432];
__device__ float g_pre[33554432];
__device__ float g_pu[HB * 16 * 256 * 256];
__device__ float g_plw[HB * 8 * 256 * 512];
__device__ __half g_fh[33554432];
__device__ __half g_nh[33554432];
__device__ __half g_qkvh[50331648];
__device__ __half g_th[16777216];
__device__ __half g_kvh[8388608];
__device__ __half g_suh[1048576];
__device__ __half g_slh[1048576];
__device__ __half g_wh[524288];

__device__ __forceinline__ unsigned s2u(const void* p) {
    return (unsigned)__cvta_generic_to_shared(p);
}
__device__ __forceinline__ void cpa16(unsigned dst, const void* src) {
    asm volatile("cp.async.cg.shared.global [%0], [%1], 16;" :: "r"(dst), "l"(src));
}
__device__ __forceinline__ void cp_commit() { asm volatile("cp.async.commit_group;"); }
__device__ __forceinline__ void cp_wait0() { asm volatile("cp.async.wait_group 0;" ::: "memory"); }
__device__ __forceinline__ void cp_wait1() { asm volatile("cp.async.wait_group 1;" ::: "memory"); }

__device__ __forceinline__ void ldm4(unsigned* r, unsigned a) {
    asm volatile("ldmatrix.sync.aligned.m8n8.x4.shared.b16 {%0,%1,%2,%3}, [%4];"
                 : "=r"(r[0]), "=r"(r[1]), "=r"(r[2]), "=r"(r[3]) : "r"(a));
}
__device__ __forceinline__ void ldm4t(unsigned* r, unsigned a) {
    asm volatile("ldmatrix.sync.aligned.m8n8.x4.trans.shared.b16 {%0,%1,%2,%3}, [%4];"
                 : "=r"(r[0]), "=r"(r[1]), "=r"(r[2]), "=r"(r[3]) : "r"(a));
}
__device__ __forceinline__ void mma_f16(float* c, const unsigned* a, unsigned b0, unsigned b1) {
    asm volatile(
        "mma.sync.aligned.m16n8k16.row.col.f32.f16.f16.f32 "
        "{%0,%1,%2,%3},{%4,%5,%6,%7},{%8,%9},{%0,%1,%2,%3};"
        : "+f"(c[0]), "+f"(c[1]), "+f"(c[2]), "+f"(c[3])
        : "r"(a[0]), "r"(a[1]), "r"(a[2]), "r"(a[3]), "r"(b0), "r"(b1));
}
__device__ __forceinline__ h2 hi2(float a, float b) {
    return __floats2half2_rn(a, b);
}
__device__ __forceinline__ float gelu_exact(float x) {
    return 0.5f * x * (1.0f + erff(x * 0.70710678118654752f));
}
__device__ __forceinline__ float brsum(float v, float* sb) {
    int t = threadIdx.x;
    sb[t] = v; __syncthreads();
    for (int s = 128; s > 0; s >>= 1) { if (t < s) sb[t] += sb[t + s]; __syncthreads(); }
    float r = sb[0]; __syncthreads(); return r;
}
__device__ __forceinline__ float brmax(float v, float* sb) {
    int t = threadIdx.x;
    sb[t] = v; __syncthreads();
    for (int s = 128; s > 0; s >>= 1) { if (t < s) sb[t] = fmaxf(sb[t], sb[t + s]); __syncthreads(); }
    float r = sb[0]; __syncthreads(); return r;
}

#define SUBB 18944             // one 32-k sub-block: Ah(10240) + Bh(8704)
#define CBUF2 37888            // two sub-blocks = 64-k block
#define CSMEM3 113664          // 3 buffers
#define NSUB 20480             // NT sub-block: Qh + Kh
#define NBUF2 40960
#define NSMEM 81920

// conv1x1 GEMM (fp16, 64-k blocks, one sync per block):
// C[b](M x GN) = Ah[b](M x K) @ Bh[b](K x GN); M = 128*gridDim.y
// epi bits: 1 gelu, 2 +R, 8 fp32 out, 32 half out. Row-group stride oGrp.
__global__ __launch_bounds__(256, 2)
void gemm_cp(const __half* __restrict__ Ah, size_t aBs,
             const __half* __restrict__ Bh, size_t bBs,
             float* __restrict__ C, __half* __restrict__ Ch,
             size_t cBs, size_t oGrp, const float* __restrict__ R,
             int K, int epi) {
    extern __shared__ char smem[];
    int tid = threadIdx.x, wid = tid >> 5, lane = tid & 31;
    int wm = wid & 1, wn = wid >> 1;
    int oBase = blockIdx.y * 128, nBase = blockIdx.x * 128;
    int b = blockIdx.z;
    Ah += (size_t)b * aBs;
    Bh += (size_t)b * bBs;

    unsigned sb0 = s2u(smem);
    // stage one 64-k block (two 32-k sub-blocks) into buffer `buf`
    auto stage = [&](int kk, int buf) {
        unsigned base = sb0 + buf * CBUF2;
#pragma unroll
        for (int sub = 0; sub < 2; sub++) {
            int k0 = kk + sub * 32;
            unsigned sbase = base + sub * SUBB;
#pragma unroll
            for (int i = 0; i < 4; i++) {
                int c = tid + 256 * i;
                if (i < 2) {
                    int r = c >> 2, s = c & 3;
                    const __half* src = Ah + (size_t)(oBase + r) * K + k0 + s * 8;
                    cpa16(sbase + r * 80 + s * 16, src);
                } else {
                    int c2 = c - 512;
                    int r = c2 >> 4, s = c2 & 15;
                    const __half* src = Bh + (size_t)(k0 + r) * GN + nBase + s * 8;
                    cpa16(sbase + 10240 + r * 272 + s * 16, src);
                }
            }
        }
        cp_commit();
    };

    float acc[4][4][4];
#pragma unroll
    for (int i = 0; i < 4; i++)
#pragma unroll
        for (int j = 0; j < 4; j++)
#pragma unroll
            for (int q = 0; q < 4; q++) acc[i][j][q] = 0.0f;

    unsigned aRow = (unsigned)(wm * 64 + (lane & 15));
    unsigned aKof = (unsigned)((lane >> 4) * 8);
    unsigned bKrow = (unsigned)((lane & 7) + ((lane >> 3) & 1) * 8);
    unsigned bNcol = (unsigned)(wn * 32 + ((lane >> 4) & 1) * 8);

    int KT = K >> 6;                 // 64-k blocks
    stage(0, 0);
    if (KT > 1) stage(64, 1);
    int buf = 0;
    for (int t = 0; t < KT; t++) {
        if (t + 2 < KT) cp_wait1(); else cp_wait0();
        __syncthreads();
        if (t + 2 < KT) {
            int nb = buf + 2; if (nb >= 3) nb -= 3;
            stage((t + 2) * 64, nb);
        }

#pragma unroll
        for (int sub = 0; sub < 2; sub++) {
            const __half* sA0 = (const __half*)(smem + buf * CBUF2 + sub * SUBB);
            const __half* sB0 = (const __half*)(smem + buf * CBUF2 + sub * SUBB + 10240);
#pragma unroll
            for (int ks = 0; ks < 32; ks += 16) {
                unsigned ah[4][4], bh2r[2][4];
#pragma unroll
                for (int mt = 0; mt < 4; mt++)
                    ldm4(ah[mt], s2u(&sA0[(aRow + mt * 16) * 40 + ks + aKof]));
#pragma unroll
                for (int n2 = 0; n2 < 2; n2++)
                    ldm4t(bh2r[n2], s2u(&sB0[(bKrow + ks) * 136 + bNcol + n2 * 16]));
#pragma unroll
                for (int mt = 0; mt < 4; mt++)
#pragma unroll
                    for (int nt = 0; nt < 4; nt++)
                        mma_f16(acc[mt][nt], ah[mt], bh2r[nt >> 1][(nt & 1) * 2],
                                bh2r[nt >> 1][(nt & 1) * 2 + 1]);
            }
        }
        buf++; if (buf >= 3) buf -= 3;
    }

    int g = lane >> 2, tg = lane & 3;
#pragma unroll
    for (int mt = 0; mt < 4; mt++) {
#pragma unroll
        for (int nt = 0; nt < 4; nt++) {
            int r0 = oBase + wm * 64 + mt * 16 + g;
            int col = nBase + wn * 32 + nt * 8 + tg * 2;
            float* c = acc[mt][nt];
#pragma unroll
            for (int h2i = 0; h2i < 2; h2i++) {
                int rr = r0 + h2i * 8;
                size_t base = (size_t)(rr >> 8) * oGrp + (size_t)b * cBs
                            + (size_t)(rr & 255) * GN + col;
                float o0 = c[2 * h2i], o1 = c[2 * h2i + 1];
                if (epi & 2) {
                    float2 rv = *(const float2*)&R[base];
                    o0 += rv.x; o1 += rv.y;
                }
                if (epi & 1) { o0 = gelu_exact(o0); o1 = gelu_exact(o1); }
                if (epi & 8) *(float2*)&C[base] = make_float2(o0, o1);
                if (epi & 32) *(h2*)&Ch[base] = hi2(o0, o1);
            }
        }
    }
}

// NT score GEMM (fp16, 64-n blocks): P[z][i][j] = sum_{n in chunk} Qh[i][n] Kh[j][n]
__global__ __launch_bounds__(256, 2)
void gemmnt_cp(const __half* __restrict__ Qh, size_t qBs,
               const __half* __restrict__ Kh, size_t kBs,
               float* __restrict__ P, int J, int nsplit) {
    extern __shared__ char smem[];
    int tid = threadIdx.x, wid = tid >> 5, lane = tid & 31;
    int wm = wid & 1, wn = wid >> 1;
    int z = blockIdx.z, b = z / nsplit, s = z % nsplit;
    Qh += (size_t)b * qBs;
    Kh += (size_t)b * kBs;
    int iBase = blockIdx.y * 128, jBase = blockIdx.x * 128;
    const int chunk = GN / nsplit;
    int n0 = s * chunk;
    unsigned sb0 = s2u(smem);

    auto stage = [&](int kk, int buf) {
        unsigned base = sb0 + buf * NBUF2;
#pragma unroll
        for (int sub = 0; sub < 2; sub++) {
            int k0 = kk + sub * 32;
            unsigned sbase = base + sub * NSUB;
#pragma unroll
            for (int i = 0; i < 4; i++) {
                int c = tid + 256 * i;
                int p = c >> 9, c2 = c & 511;
                int r = c2 >> 2, sg = c2 & 3;
                const __half* src = (p ? Kh + (size_t)(jBase + r) * GN
                                       : Qh + (size_t)(iBase + r) * GN) + n0 + k0 + sg * 8;
                cpa16(sbase + p * 10240 + r * 80 + sg * 16, src);
            }
        }
        cp_commit();
    };

    float acc[4][4][4];
#pragma unroll
    for (int i = 0; i < 4; i++)
#pragma unroll
        for (int j = 0; j < 4; j++)
#pragma unroll
            for (int q = 0; q < 4; q++) acc[i][j][q] = 0.0f;

    unsigned aRow = (unsigned)(wm * 64 + (lane & 15));
    unsigned aKof = (unsigned)((lane >> 4) * 8);
    unsigned bJrow = (unsigned)(wn * 32 + (lane & 7) + ((lane >> 4) & 1) * 8);
    unsigned bKof = (unsigned)(((lane >> 3) & 1) * 8);

    int KT = chunk >> 6;
    stage(0, 0);
    for (int t = 0; t < KT; t++) {
        int cb = t & 1;
        if (t + 1 < KT) {
            stage((t + 1) * 64, cb ^ 1);
            cp_wait1();
        } else {
            cp_wait0();
        }
        __syncthreads();

#pragma unroll
        for (int sub = 0; sub < 2; sub++) {
            const __half* sQ0 = (const __half*)(smem + cb * NBUF2 + sub * NSUB);
            const __half* sK0 = (const __half*)(smem + cb * NBUF2 + sub * NSUB + 10240);
#pragma unroll
            for (int ks = 0; ks < 32; ks += 16) {
                unsigned ah[4][4], bh2r[2][4];
#pragma unroll
                for (int mt = 0; mt < 4; mt++)
                    ldm4(ah[mt], s2u(&sQ0[(aRow + mt * 16) * 40 + ks + aKof]));
#pragma unroll
                for (int n2 = 0; n2 < 2; n2++)
                    ldm4(bh2r[n2], s2u(&sK0[(bJrow + n2 * 16) * 40 + ks + bKof]));
#pragma unroll
                for (int mt = 0; mt < 4; mt++)
#pragma unroll
                    for (int nt = 0; nt < 4; nt++)
                        mma_f16(acc[mt][nt], ah[mt], bh2r[nt >> 1][(nt & 1) * 2],
                                bh2r[nt >> 1][(nt & 1) * 2 + 1]);
            }
        }
        __syncthreads();
    }

    int g = lane >> 2, tg = lane & 3;
#pragma unroll
    for (int mt = 0; mt < 4; mt++) {
#pragma unroll
        for (int nt = 0; nt < 4; nt++) {
            int r0 = iBase + wm * 64 + mt * 16 + g;
            int col = jBase + wn * 32 + nt * 8 + tg * 2;
            float* c = acc[mt][nt];
#pragma unroll
            for (int h2i = 0; h2i < 2; h2i++) {
                size_t base = ((size_t)z * 256 + r0 + h2i * 8) * J + col;
                *(float2*)&P[base] = make_float2(c[2 * h2i], c[2 * h2i + 1]);
            }
        }
    }
}

__global__ __launch_bounds__(256)
void split_w8(const float* w0, const float* w1, const float* w2, const float* w3,
              const float* w4, const float* w5, const float* w6, const float* w7,
              __half* __restrict__ H) {
    const float* srcs[8] = { w0, w1, w2, w3, w4, w5, w6, w7 };
    int w = blockIdx.y;
    const float* X = srcs[w];
    int i = blockIdx.x * 256 + threadIdx.x;
    float4 v = ((const float4*)X)[i];
    size_t o = (size_t)w * 32768 + 2 * i;
    ((h2*)H)[o] = hi2(v.x, v.y);
    ((h2*)H)[o + 1] = hi2(v.z, v.w);
}

__global__ __launch_bounds__(256)
void split_hi(const float* __restrict__ X, __half* __restrict__ H, int n4) {
    int i = blockIdx.x * 256 + threadIdx.x;
    if (i < n4) {
        float4 v = ((const float4*)X)[i];
        ((h2*)H)[2 * i] = hi2(v.x, v.y);
        ((h2*)H)[2 * i + 1] = hi2(v.z, v.w);
    }
}

__global__ __launch_bounds__(256)
void inorm_hi(const float* __restrict__ X, __half* __restrict__ H,
              const float* __restrict__ gamma, const float* __restrict__ beta) {
    __shared__ float sb[256];
    int row = blockIdx.x, cch = row & (ECH - 1);
    const float4* xr = (const float4*)(X + (size_t)row * GN);
    h2* hr = (h2*)(H + (size_t)row * GN);
    float s = 0.f, ss = 0.f;
    for (int i = threadIdx.x; i < GN / 4; i += 256) {
        float4 v = xr[i];
        s += v.x + v.y + v.z + v.w;
        ss += v.x * v.x + v.y * v.y + v.z * v.z + v.w * v.w;
    }
    float tot = brsum(s, sb), tot2 = brsum(ss, sb);
    const float inv = 1.0f / (float)GN;
    float mu = tot * inv, var = tot2 * inv - mu * mu;
    float rstd = rsqrtf(var + 1e-5f);
    float a = rstd * gamma[cch], bb = beta[cch] - mu * a;
    for (int i = threadIdx.x; i < GN / 4; i += 256) {
        float4 v = xr[i];
        hr[2 * i] = hi2(v.x * a + bb, v.y * a + bb);
        hr[2 * i + 1] = hi2(v.z * a + bb, v.w * a + bb);
    }
}

__global__ __launch_bounds__(256)
void softmax_hi(const float* __restrict__ P, __half* __restrict__ SH,
                int J, float scale, int nsplit) {
    __shared__ float rowbuf[512];
    __shared__ float sb[256];
    int row = blockIdx.x, b = row >> 8, i = row & 255, tid = threadIdx.x;
    for (int j = tid; j < J; j += 256) {
        float v = 0.f;
        for (int s = 0; s < nsplit; s++)
            v += P[(((size_t)(b * nsplit + s) * 256) + i) * J + j];
        rowbuf[j] = v * scale;
    }
    __syncthreads();
    float ls = 0.f;
    for (int j = tid; j < J; j += 256) ls += rowbuf[j];
    float mean = brsum(ls, sb) / (float)J;
    float lv = 0.f;
    for (int j = tid; j < J; j += 256) { float d = rowbuf[j] - mean; lv += d * d; }
    float rstd = rsqrtf(brsum(lv, sb) / (float)J + 1e-5f);
    float lm = -1e30f;
    for (int j = tid; j < J; j += 256) {
        float tt = (rowbuf[j] - mean) * rstd;
        rowbuf[j] = tt;
        lm = fmaxf(lm, tt);
    }
    float mx = brmax(lm, sb);
    float le = 0.f;
    for (int j = tid; j < J; j += 256) {
        float e = expf(rowbuf[j] - mx);
        rowbuf[j] = e;
        le += e;
    }
    float rden = 1.0f / brsum(le, sb);
    size_t ob = ((size_t)b * 256 + i) * J;
    for (int j = tid; j < J; j += 256)
        SH[ob + j] = __float2half_rn(rowbuf[j] * rden);
}

extern "C" void kernel_launch(void* const* d_in, const int* in_sizes, int n_in,
                              void* d_out, int out_size) {
    const float* feat = (const float*)d_in[0];
    const float* kv   = (const float*)d_in[1];
    const float* ag = (const float*)d_in[10];
    const float* ab = (const float*)d_in[11];
    const float* eg = (const float*)d_in[12];
    const float* eb = (const float*)d_in[13];
    float* out = (float*)d_out;

    float *emb, *pre, *pu, *plw;
    __half *fh, *nh, *qkvh, *th, *kvh, *suh, *slh, *wh;
    cudaGetSymbolAddress((void**)&emb, g_emb);
    cudaGetSymbolAddress((void**)&pre, g_pre);
    cudaGetSymbolAddress((void**)&pu, g_pu);
    cudaGetSymbolAddress((void**)&plw, g_plw);
    cudaGetSymbolAddress((void**)&fh, g_fh);
    cudaGetSymbolAddress((void**)&nh, g_nh);
    cudaGetSymbolAddress((void**)&qkvh, g_qkvh);
    cudaGetSymbolAddress((void**)&th, g_th);
    cudaGetSymbolAddress((void**)&kvh, g_kvh);
    cudaGetSymbolAddress((void**)&suh, g_suh);
    cudaGetSymbolAddress((void**)&slh, g_slh);
    cudaGetSymbolAddress((void**)&wh, g_wh);

    __half *qh = qkvh;
    __half *kh = qkvh + TOT4;
    __half *vh = qkvh + 2 * TOT4;

    cudaFuncSetAttribute(gemm_cp, cudaFuncAttributeMaxDynamicSharedMemorySize, CSMEM3);
    cudaFuncSetAttribute(gemmnt_cp, cudaFuncAttributeMaxDynamicSharedMemorySize, NSMEM);

    const float scale = 1.0f / 128.0f;
    dim3 blk(256);
    dim3 g8(GN / 128, 2, 8);
    dim3 g4(GN / 128, 2, 4);

    // #1 weights
    split_w8<<<dim3(64, 8), blk>>>((const float*)d_in[2], (const float*)d_in[3],
                                   (const float*)d_in[4], (const float*)d_in[5],
                                   (const float*)d_in[6], (const float*)d_in[7],
                                   (const float*)d_in[8], (const float*)d_in[9], wh);
    // #2 feat, #3 kv
    split_hi<<<32768, blk>>>(feat, fh, 8388608);
    split_hi<<<8192, blk>>>(kv, kvh, 2097152);
    // #4 emb = gelu(w_in @ feat)
    gemm_cp<<<g8, blk, CSMEM3>>>(wh, 0, fh, BSTR, emb, nullptr,
                                 BSTR, 0, nullptr, 256, 1 | 8);
    // #5 nrm hi plane
    inorm_hi<<<NB * ECH, blk>>>(emb, nh, ag, ab);
    // #6 fused QKV (M=768) -> PROFILED
    gemm_cp<<<dim3(GN / 128, 6, 4), blk, CSMEM3>>>(wh + 2 * 65536, 0,
                                                   nh + TOT4, BSTR,
                                                   nullptr, qkvh, BSTR, TOT4,
                                                   nullptr, 256, 32);
    // #7 upper scores (nsplit=16 -> 256 CTAs)
    gemmnt_cp<<<dim3(2, 2, HB * 16), blk, NSMEM>>>(qh, BSTR, kh, BSTR, pu, 256, 16);
    // #8 softmax upper
    softmax_hi<<<HB * 256, blk>>>(pu, suh, 256, scale, 16);
    // #9 t = su @ v
    gemm_cp<<<g4, blk, CSMEM3>>>(suh, 65536, vh, BSTR, nullptr, th,
                                 BSTR, 0, nullptr, 256, 32);
    // #10 pre_u = wo_sa @ t + emb_u
    gemm_cp<<<g4, blk, CSMEM3>>>(wh + 5 * 65536, 0, th, BSTR,
                                 pre + TOT4, nullptr, BSTR, 0,
                                 emb + TOT4, 256, 2 | 8);
    // #11 lower Ql
    gemm_cp<<<g4, blk, CSMEM3>>>(wh + 6 * 65536, 0, nh, BSTR,
                                 nullptr, qh, BSTR, 0, nullptr, 256, 32);
    // #12 lower scores (nsplit=8, kv shared)
    gemmnt_cp<<<dim3(4, 2, HB * 8), blk, NSMEM>>>(qh, BSTR, kvh, 0, plw, 512, 8);
    // #13 softmax lower
    softmax_hi<<<HB * 256, blk>>>(plw, slh, 512, scale, 8);
    // #14 ca = sl @ kv (K=512)
    gemm_cp<<<g4, blk, CSMEM3>>>(slh, 131072, kvh, 0, nullptr, th,
                                 BSTR, 0, nullptr, 512, 32);
    // #15 pre_l = wo_ca @ ca + emb_l
    gemm_cp<<<g4, blk, CSMEM3>>>(wh + 7 * 65536, 0, th, BSTR,
                                 pre, nullptr, BSTR, 0, emb, 256, 2 | 8);
    // #16 nrm2
    inorm_hi<<<NB * ECH, blk>>>(pre, nh, eg, eb);
    // #17 out = gelu(w_out @ nrm2)
    gemm_cp<<<g8, blk, CSMEM3>>>(wh + 65536, 0, nh, BSTR, out, nullptr,
                                 BSTR, 0, nullptr, 256, 1 | 8);
}

// round 16
// speedup vs baseline: 2.0906x; 1.0688x over previous
#include <cuda_runtime.h>
#include <cuda_fp16.h>
#include <math.h>

#define GN 16384
#define ECH 256
#define NB 8
#define HB 4
static const size_t BSTR = (size_t)ECH * GN;
static const size_t TOT4 = (size_t)HB * BSTR;
typedef __half2 h2;

__device__ __half g_emb[33554432];              // fp16 intermediate
__device__ __half g_pre[33554432];              // fp16 intermediate
__device__ float g_pu[HB * 16 * 256 * 256];
__device__ float g_plw[HB * 8 * 256 * 512];
__device__ __half g_fh[33554432];
__device__ __half g_nh[33554432];
__device__ __half g_qkvh[50331648];
__device__ __half g_th[16777216];
__device__ __half g_kvh[8388608];
__device__ __half g_suh[1048576];
__device__ __half g_slh[1048576];
__device__ __half g_wh[524288];

__device__ __forceinline__ unsigned s2u(const void* p) {
    return (unsigned)__cvta_generic_to_shared(p);
}
__device__ __forceinline__ void cpa16(unsigned dst, const void* src) {
    asm volatile("cp.async.cg.shared.global [%0], [%1], 16;" :: "r"(dst), "l"(src));
}
__device__ __forceinline__ void cp_commit() { asm volatile("cp.async.commit_group;"); }
__device__ __forceinline__ void cp_wait0() { asm volatile("cp.async.wait_group 0;" ::: "memory"); }
__device__ __forceinline__ void cp_wait1() { asm volatile("cp.async.wait_group 1;" ::: "memory"); }

__device__ __forceinline__ void ldm4(unsigned* r, unsigned a) {
    asm volatile("ldmatrix.sync.aligned.m8n8.x4.shared.b16 {%0,%1,%2,%3}, [%4];"
                 : "=r"(r[0]), "=r"(r[1]), "=r"(r[2]), "=r"(r[3]) : "r"(a));
}
__device__ __forceinline__ void ldm4t(unsigned* r, unsigned a) {
    asm volatile("ldmatrix.sync.aligned.m8n8.x4.trans.shared.b16 {%0,%1,%2,%3}, [%4];"
                 : "=r"(r[0]), "=r"(r[1]), "=r"(r[2]), "=r"(r[3]) : "r"(a));
}
__device__ __forceinline__ void mma_f16(float* c, const unsigned* a, unsigned b0, unsigned b1) {
    asm volatile(
        "mma.sync.aligned.m16n8k16.row.col.f32.f16.f16.f32 "
        "{%0,%1,%2,%3},{%4,%5,%6,%7},{%8,%9},{%0,%1,%2,%3};"
        : "+f"(c[0]), "+f"(c[1]), "+f"(c[2]), "+f"(c[3])
        : "r"(a[0]), "r"(a[1]), "r"(a[2]), "r"(a[3]), "r"(b0), "r"(b1));
}
__device__ __forceinline__ h2 hi2(float a, float b) {
    return __floats2half2_rn(a, b);
}
__device__ __forceinline__ float gelu_exact(float x) {
    return 0.5f * x * (1.0f + erff(x * 0.70710678118654752f));
}
__device__ __forceinline__ float brsum(float v, float* sb) {
    int t = threadIdx.x;
    sb[t] = v; __syncthreads();
    for (int s = 128; s > 0; s >>= 1) { if (t < s) sb[t] += sb[t + s]; __syncthreads(); }
    float r = sb[0]; __syncthreads(); return r;
}
__device__ __forceinline__ float brmax(float v, float* sb) {
    int t = threadIdx.x;
    sb[t] = v; __syncthreads();
    for (int s = 128; s > 0; s >>= 1) { if (t < s) sb[t] = fmaxf(sb[t], sb[t + s]); __syncthreads(); }
    float r = sb[0]; __syncthreads(); return r;
}

#define SUBB 18944
#define CBUF2 37888
#define CSMEM3 113664
#define NSUB 20480
#define NBUF2 40960
#define NSMEM 81920

// conv1x1 GEMM (fp16, 64-k blocks): C[b](M x GN) = Ah[b](M x K) @ Bh[b](K x GN)
// epi bits: 1 gelu, 2 +R(half), 8 fp32 out C, 32 half out Ch. Row-group stride oGrp.
__global__ __launch_bounds__(256, 2)
void gemm_cp(const __half* __restrict__ Ah, size_t aBs,
             const __half* __restrict__ Bh, size_t bBs,
             float* __restrict__ C, __half* __restrict__ Ch,
             size_t cBs, size_t oGrp, const __half* __restrict__ R,
             int K, int epi) {
    extern __shared__ char smem[];
    int tid = threadIdx.x, wid = tid >> 5, lane = tid & 31;
    int wm = wid & 1, wn = wid >> 1;
    int oBase = blockIdx.y * 128, nBase = blockIdx.x * 128;
    int b = blockIdx.z;
    Ah += (size_t)b * aBs;
    Bh += (size_t)b * bBs;

    unsigned sb0 = s2u(smem);
    auto stage = [&](int kk, int buf) {
        unsigned base = sb0 + buf * CBUF2;
#pragma unroll
        for (int sub = 0; sub < 2; sub++) {
            int k0 = kk + sub * 32;
            unsigned sbase = base + sub * SUBB;
#pragma unroll
            for (int i = 0; i < 4; i++) {
                int c = tid + 256 * i;
                if (i < 2) {
                    int r = c >> 2, s = c & 3;
                    const __half* src = Ah + (size_t)(oBase + r) * K + k0 + s * 8;
                    cpa16(sbase + r * 80 + s * 16, src);
                } else {
                    int c2 = c - 512;
                    int r = c2 >> 4, s = c2 & 15;
                    const __half* src = Bh + (size_t)(k0 + r) * GN + nBase + s * 8;
                    cpa16(sbase + 10240 + r * 272 + s * 16, src);
                }
            }
        }
        cp_commit();
    };

    float acc[4][4][4];
#pragma unroll
    for (int i = 0; i < 4; i++)
#pragma unroll
        for (int j = 0; j < 4; j++)
#pragma unroll
            for (int q = 0; q < 4; q++) acc[i][j][q] = 0.0f;

    unsigned aRow = (unsigned)(wm * 64 + (lane & 15));
    unsigned aKof = (unsigned)((lane >> 4) * 8);
    unsigned bKrow = (unsigned)((lane & 7) + ((lane >> 3) & 1) * 8);
    unsigned bNcol = (unsigned)(wn * 32 + ((lane >> 4) & 1) * 8);

    int KT = K >> 6;
    stage(0, 0);
    if (KT > 1) stage(64, 1);
    int buf = 0;
    for (int t = 0; t < KT; t++) {
        if (t + 2 < KT) cp_wait1(); else cp_wait0();
        __syncthreads();
        if (t + 2 < KT) {
            int nb = buf + 2; if (nb >= 3) nb -= 3;
            stage((t + 2) * 64, nb);
        }

#pragma unroll
        for (int sub = 0; sub < 2; sub++) {
            const __half* sA0 = (const __half*)(smem + buf * CBUF2 + sub * SUBB);
            const __half* sB0 = (const __half*)(smem + buf * CBUF2 + sub * SUBB + 10240);
#pragma unroll
            for (int ks = 0; ks < 32; ks += 16) {
                unsigned ah[4][4], bh2r[2][4];
#pragma unroll
                for (int mt = 0; mt < 4; mt++)
                    ldm4(ah[mt], s2u(&sA0[(aRow + mt * 16) * 40 + ks + aKof]));
#pragma unroll
                for (int n2 = 0; n2 < 2; n2++)
                    ldm4t(bh2r[n2], s2u(&sB0[(bKrow + ks) * 136 + bNcol + n2 * 16]));
#pragma unroll
                for (int mt = 0; mt < 4; mt++)
#pragma unroll
                    for (int nt = 0; nt < 4; nt++)
                        mma_f16(acc[mt][nt], ah[mt], bh2r[nt >> 1][(nt & 1) * 2],
                                bh2r[nt >> 1][(nt & 1) * 2 + 1]);
            }
        }
        buf++; if (buf >= 3) buf -= 3;
    }

    int g = lane >> 2, tg = lane & 3;
#pragma unroll
    for (int mt = 0; mt < 4; mt++) {
#pragma unroll
        for (int nt = 0; nt < 4; nt++) {
            int r0 = oBase + wm * 64 + mt * 16 + g;
            int col = nBase + wn * 32 + nt * 8 + tg * 2;
            float* c = acc[mt][nt];
#pragma unroll
            for (int h2i = 0; h2i < 2; h2i++) {
                int rr = r0 + h2i * 8;
                size_t base = (size_t)(rr >> 8) * oGrp + (size_t)b * cBs
                            + (size_t)(rr & 255) * GN + col;
                float o0 = c[2 * h2i], o1 = c[2 * h2i + 1];
                if (epi & 2) {
                    float2 rv = __half22float2(*(const h2*)&R[base]);
                    o0 += rv.x; o1 += rv.y;
                }
                if (epi & 1) { o0 = gelu_exact(o0); o1 = gelu_exact(o1); }
                if (epi & 8) *(float2*)&C[base] = make_float2(o0, o1);
                if (epi & 32) *(h2*)&Ch[base] = hi2(o0, o1);
            }
        }
    }
}

// NT score GEMM (fp16, 64-n blocks): P[z][i][j] = sum_{n in chunk} Qh[i][n] Kh[j][n]
__global__ __launch_bounds__(256, 2)
void gemmnt_cp(const __half* __restrict__ Qh, size_t qBs,
               const __half* __restrict__ Kh, size_t kBs,
               float* __restrict__ P, int J, int nsplit) {
    extern __shared__ char smem[];
    int tid = threadIdx.x, wid = tid >> 5, lane = tid & 31;
    int wm = wid & 1, wn = wid >> 1;
    int z = blockIdx.z, b = z / nsplit, s = z % nsplit;
    Qh += (size_t)b * qBs;
    Kh += (size_t)b * kBs;
    int iBase = blockIdx.y * 128, jBase = blockIdx.x * 128;
    const int chunk = GN / nsplit;
    int n0 = s * chunk;
    unsigned sb0 = s2u(smem);

    auto stage = [&](int kk, int buf) {
        unsigned base = sb0 + buf * NBUF2;
#pragma unroll
        for (int sub = 0; sub < 2; sub++) {
            int k0 = kk + sub * 32;
            unsigned sbase = base + sub * NSUB;
#pragma unroll
            for (int i = 0; i < 4; i++) {
                int c = tid + 256 * i;
                int p = c >> 9, c2 = c & 511;
                int r = c2 >> 2, sg = c2 & 3;
                const __half* src = (p ? Kh + (size_t)(jBase + r) * GN
                                       : Qh + (size_t)(iBase + r) * GN) + n0 + k0 + sg * 8;
                cpa16(sbase + p * 10240 + r * 80 + sg * 16, src);
            }
        }
        cp_commit();
    };

    float acc[4][4][4];
#pragma unroll
    for (int i = 0; i < 4; i++)
#pragma unroll
        for (int j = 0; j < 4; j++)
#pragma unroll
            for (int q = 0; q < 4; q++) acc[i][j][q] = 0.0f;

    unsigned aRow = (unsigned)(wm * 64 + (lane & 15));
    unsigned aKof = (unsigned)((lane >> 4) * 8);
    unsigned bJrow = (unsigned)(wn * 32 + (lane & 7) + ((lane >> 4) & 1) * 8);
    unsigned bKof = (unsigned)(((lane >> 3) & 1) * 8);

    int KT = chunk >> 6;
    stage(0, 0);
    for (int t = 0; t < KT; t++) {
        int cb = t & 1;
        if (t + 1 < KT) {
            stage((t + 1) * 64, cb ^ 1);
            cp_wait1();
        } else {
            cp_wait0();
        }
        __syncthreads();

#pragma unroll
        for (int sub = 0; sub < 2; sub++) {
            const __half* sQ0 = (const __half*)(smem + cb * NBUF2 + sub * NSUB);
            const __half* sK0 = (const __half*)(smem + cb * NBUF2 + sub * NSUB + 10240);
#pragma unroll
            for (int ks = 0; ks < 32; ks += 16) {
                unsigned ah[4][4], bh2r[2][4];
#pragma unroll
                for (int mt = 0; mt < 4; mt++)
                    ldm4(ah[mt], s2u(&sQ0[(aRow + mt * 16) * 40 + ks + aKof]));
#pragma unroll
                for (int n2 = 0; n2 < 2; n2++)
                    ldm4(bh2r[n2], s2u(&sK0[(bJrow + n2 * 16) * 40 + ks + bKof]));
#pragma unroll
                for (int mt = 0; mt < 4; mt++)
#pragma unroll
                    for (int nt = 0; nt < 4; nt++)
                        mma_f16(acc[mt][nt], ah[mt], bh2r[nt >> 1][(nt & 1) * 2],
                                bh2r[nt >> 1][(nt & 1) * 2 + 1]);
            }
        }
        __syncthreads();
    }

    int g = lane >> 2, tg = lane & 3;
#pragma unroll
    for (int mt = 0; mt < 4; mt++) {
#pragma unroll
        for (int nt = 0; nt < 4; nt++) {
            int r0 = iBase + wm * 64 + mt * 16 + g;
            int col = jBase + wn * 32 + nt * 8 + tg * 2;
            float* c = acc[mt][nt];
#pragma unroll
            for (int h2i = 0; h2i < 2; h2i++) {
                size_t base = ((size_t)z * 256 + r0 + h2i * 8) * J + col;
                *(float2*)&P[base] = make_float2(c[2 * h2i], c[2 * h2i + 1]);
            }
        }
    }
}

__global__ __launch_bounds__(256)
void split_w8(const float* w0, const float* w1, const float* w2, const float* w3,
              const float* w4, const float* w5, const float* w6, const float* w7,
              __half* __restrict__ H) {
    const float* srcs[8] = { w0, w1, w2, w3, w4, w5, w6, w7 };
    int w = blockIdx.y;
    const float* X = srcs[w];
    int i = blockIdx.x * 256 + threadIdx.x;
    float4 v = ((const float4*)X)[i];
    size_t o = (size_t)w * 32768 + 2 * i;
    ((h2*)H)[o] = hi2(v.x, v.y);
    ((h2*)H)[o + 1] = hi2(v.z, v.w);
}

__global__ __launch_bounds__(256)
void split_hi(const float* __restrict__ X, __half* __restrict__ H, int n4) {
    int i = blockIdx.x * 256 + threadIdx.x;
    if (i < n4) {
        float4 v = ((const float4*)X)[i];
        ((h2*)H)[2 * i] = hi2(v.x, v.y);
        ((h2*)H)[2 * i + 1] = hi2(v.z, v.w);
    }
}

// instance norm over half input -> half output
__global__ __launch_bounds__(256)
void inorm_hh(const __half* __restrict__ X, __half* __restrict__ H,
              const float* __restrict__ gamma, const float* __restrict__ beta) {
    __shared__ float sb[256];
    int row = blockIdx.x, cch = row & (ECH - 1);
    const h2* xr = (const h2*)(X + (size_t)row * GN);
    h2* hr = (h2*)(H + (size_t)row * GN);
    float s = 0.f, ss = 0.f;
    for (int i = threadIdx.x; i < GN / 2; i += 256) {
        float2 v = __half22float2(xr[i]);
        s += v.x + v.y;
        ss += v.x * v.x + v.y * v.y;
    }
    float tot = brsum(s, sb), tot2 = brsum(ss, sb);
    const float inv = 1.0f / (float)GN;
    float mu = tot * inv, var = tot2 * inv - mu * mu;
    float rstd = rsqrtf(var + 1e-5f);
    float a = rstd * gamma[cch], bb = beta[cch] - mu * a;
    for (int i = threadIdx.x; i < GN / 2; i += 256) {
        float2 v = __half22float2(xr[i]);
        hr[i] = hi2(v.x * a + bb, v.y * a + bb);
    }
}

__global__ __launch_bounds__(256)
void softmax_hi(const float* __restrict__ P, __half* __restrict__ SH,
                int J, float scale, int nsplit) {
    __shared__ float rowbuf[512];
    __shared__ float sb[256];
    int row = blockIdx.x, b = row >> 8, i = row & 255, tid = threadIdx.x;
    for (int j = tid; j < J; j += 256) {
        float v = 0.f;
        for (int s = 0; s < nsplit; s++)
            v += P[(((size_t)(b * nsplit + s) * 256) + i) * J + j];
        rowbuf[j] = v * scale;
    }
    __syncthreads();
    float ls = 0.f;
    for (int j = tid; j < J; j += 256) ls += rowbuf[j];
    float mean = brsum(ls, sb) / (float)J;
    float lv = 0.f;
    for (int j = tid; j < J; j += 256) { float d = rowbuf[j] - mean; lv += d * d; }
    float rstd = rsqrtf(brsum(lv, sb) / (float)J + 1e-5f);
    float lm = -1e30f;
    for (int j = tid; j < J; j += 256) {
        float tt = (rowbuf[j] - mean) * rstd;
        rowbuf[j] = tt;
        lm = fmaxf(lm, tt);
    }
    float mx = brmax(lm, sb);
    float le = 0.f;
    for (int j = tid; j < J; j += 256) {
        float e = expf(rowbuf[j] - mx);
        rowbuf[j] = e;
        le += e;
    }
    float rden = 1.0f / brsum(le, sb);
    size_t ob = ((size_t)b * 256 + i) * J;
    for (int j = tid; j < J; j += 256)
        SH[ob + j] = __float2half_rn(rowbuf[j] * rden);
}

extern "C" void kernel_launch(void* const* d_in, const int* in_sizes, int n_in,
                              void* d_out, int out_size) {
    const float* feat = (const float*)d_in[0];
    const float* kv   = (const float*)d_in[1];
    const float* ag = (const float*)d_in[10];
    const float* ab = (const float*)d_in[11];
    const float* eg = (const float*)d_in[12];
    const float* eb = (const float*)d_in[13];
    float* out = (float*)d_out;

    float *pu, *plw;
    __half *emb, *pre, *fh, *nh, *qkvh, *th, *kvh, *suh, *slh, *wh;
    cudaGetSymbolAddress((void**)&emb, g_emb);
    cudaGetSymbolAddress((void**)&pre, g_pre);
    cudaGetSymbolAddress((void**)&pu, g_pu);
    cudaGetSymbolAddress((void**)&plw, g_plw);
    cudaGetSymbolAddress((void**)&fh, g_fh);
    cudaGetSymbolAddress((void**)&nh, g_nh);
    cudaGetSymbolAddress((void**)&qkvh, g_qkvh);
    cudaGetSymbolAddress((void**)&th, g_th);
    cudaGetSymbolAddress((void**)&kvh, g_kvh);
    cudaGetSymbolAddress((void**)&suh, g_suh);
    cudaGetSymbolAddress((void**)&slh, g_slh);
    cudaGetSymbolAddress((void**)&wh, g_wh);

    __half *qh = qkvh;
    __half *kh = qkvh + TOT4;
    __half *vh = qkvh + 2 * TOT4;

    cudaFuncSetAttribute(gemm_cp, cudaFuncAttributeMaxDynamicSharedMemorySize, CSMEM3);
    cudaFuncSetAttribute(gemmnt_cp, cudaFuncAttributeMaxDynamicSharedMemorySize, NSMEM);

    const float scale = 1.0f / 128.0f;
    dim3 blk(256);
    dim3 g8(GN / 128, 2, 8);
    dim3 g4(GN / 128, 2, 4);

    // #1 weights
    split_w8<<<dim3(64, 8), blk>>>((const float*)d_in[2], (const float*)d_in[3],
                                   (const float*)d_in[4], (const float*)d_in[5],
                                   (const float*)d_in[6], (const float*)d_in[7],
                                   (const float*)d_in[8], (const float*)d_in[9], wh);
    // #2 feat, #3 kv
    split_hi<<<32768, blk>>>(feat, fh, 8388608);
    split_hi<<<8192, blk>>>(kv, kvh, 2097152);
    // #4 emb = gelu(w_in @ feat) -> half
    gemm_cp<<<g8, blk, CSMEM3>>>(wh, 0, fh, BSTR, nullptr, emb,
                                 BSTR, 0, nullptr, 256, 1 | 32);
    // #5 nrm = inorm(emb) half->half
    inorm_hh<<<NB * ECH, blk>>>(emb, nh, ag, ab);
    // #6 fused QKV (M=768) -> PROFILED
    gemm_cp<<<dim3(GN / 128, 6, 4), blk, CSMEM3>>>(wh + 2 * 65536, 0,
                                                   nh + TOT4, BSTR,
                                                   nullptr, qkvh, BSTR, TOT4,
                                                   nullptr, 256, 32);
    // #7 upper scores (nsplit=16)
    gemmnt_cp<<<dim3(2, 2, HB * 16), blk, NSMEM>>>(qh, BSTR, kh, BSTR, pu, 256, 16);
    // #8 softmax upper
    softmax_hi<<<HB * 256, blk>>>(pu, suh, 256, scale, 16);
    // #9 t = su @ v
    gemm_cp<<<g4, blk, CSMEM3>>>(suh, 65536, vh, BSTR, nullptr, th,
                                 BSTR, 0, nullptr, 256, 32);
    // #10 pre_u = wo_sa @ t + emb_u -> half
    gemm_cp<<<g4, blk, CSMEM3>>>(wh + 5 * 65536, 0, th, BSTR,
                                 nullptr, pre + TOT4, BSTR, 0,
                                 emb + TOT4, 256, 2 | 32);
    // #11 lower Ql
    gemm_cp<<<g4, blk, CSMEM3>>>(wh + 6 * 65536, 0, nh, BSTR,
                                 nullptr, qh, BSTR, 0, nullptr, 256, 32);
    // #12 lower scores (nsplit=8, kv shared)
    gemmnt_cp<<<dim3(4, 2, HB * 8), blk, NSMEM>>>(qh, BSTR, kvh, 0, plw, 512, 8);
    // #13 softmax lower
    softmax_hi<<<HB * 256, blk>>>(plw, slh, 512, scale, 8);
    // #14 ca = sl @ kv (K=512)
    gemm_cp<<<g4, blk, CSMEM3>>>(slh, 131072, kvh, 0, nullptr, th,
                                 BSTR, 0, nullptr, 512, 32);
    // #15 pre_l = wo_ca @ ca + emb_l -> half
    gemm_cp<<<g4, blk, CSMEM3>>>(wh + 7 * 65536, 0, th, BSTR,
                                 nullptr, pre, BSTR, 0, emb, 256, 2 | 32);
    // #16 nrm2 = inorm(pre) half->half
    inorm_hh<<<NB * ECH, blk>>>(pre, nh, eg, eb);
    // #17 out = gelu(w_out @ nrm2) -> fp32
    gemm_cp<<<g8, blk, CSMEM3>>>(wh + 65536, 0, nh, BSTR, out, nullptr,
                                 BSTR, 0, nullptr, 256, 1 | 8);
}